// round 11
// baseline (speedup 1.0000x reference)
#include <cuda_runtime.h>
#include <cuda_fp16.h>
#include <cstdint>

// ---------------------------------------------------------------------------
// SelectionGNN (clique+line), B=8, N=4096, E=1, K=3, F=[16,32,16]
// Diffusion GEMMs via mma.sync fp16 2-pass:
//   D = (Ah*Bh with FP32 accum) + (Al*Bh with FP16 accum, merged in epilogue)
// The lo-pass is ~2^-12 of D, so fp16 accumulation adds ~4e-6 relative error
// while running at the (2x faster) f16-accum HMMA rate.
// Operands PRE-TILED + PRE-SWIZZLED in gmem (tile = smem image), TMA bulk
// loads, full/empty mbarrier pipeline, 2 CTAs/SM (launch_bounds(256,2)).
// 16->32 layers: one fused kernel does z2 split-K sum + combine + projections
// (y32 never materialized).
// ---------------------------------------------------------------------------

#define NNODES 4096
#define BATCH  8
#define CC     128                 // channels = B*16 (GEMM M)
#define NT     128                 // n-tile per CTA
#define SPLITK 8
#define KC     (NNODES / SPLITK)   // 512 k per CTA
#define NKT    (KC / 64)           // 8 k-tiles (64 k each)
#define NKTOT  (NNODES / 64)       // 64 k-tiles total

#define ATILE_H  16384             // A tile halves (32KB): 128 rows x 256B
#define BTILE_H  8192              // B tile halves (16KB): 128 rows x 128B
#define STAGESZ  49152             // bytes: A(32K) + B(16K)
#define NSTAGE   2
#define SMEMSZ   (64 + NSTAGE * STAGESZ)   // 98368 -> 2 CTAs/SM fit

// ---------------- scratch (device globals; allocation is forbidden) --------
__device__ __align__(256) __half g_Sc2[(size_t)NNODES * NNODES];   // 32MB tiled
__device__ __align__(256) __half g_Sl2[(size_t)NNODES * NNODES];   // 32MB tiled
__device__ __align__(256) __half g_x2 [NKTOT * ATILE_H];           // 2MB tiled
__device__ __align__(256) __half g_a2 [NKTOT * ATILE_H];
__device__ __align__(256) __half g_b2 [NKTOT * ATILE_H];
__device__ __align__(256) float g_part[SPLITK * CC * NNODES];      // 16.8 MB
__device__ __align__(256) float g_z1f [CC * NNODES];
__device__ __align__(256) float g_v0  [CC * NNODES];
__device__ __align__(256) float g_v1  [CC * NNODES];
__device__ __align__(256) float g_y16 [CC * NNODES];
__device__ __align__(256) float g_hp  [8 * BATCH * 64];

// ---------------- PTX helpers (baseline sm_90-level PTX only) ---------------
__device__ __forceinline__ uint32_t smem_u32(const void* p) {
    uint32_t a;
    asm("{ .reg .u64 t; cvta.to.shared.u64 t, %1; cvt.u32.u64 %0, t; }" : "=r"(a) : "l"(p));
    return a;
}
#define MBAR_INIT(a, c) asm volatile("mbarrier.init.shared.b64 [%0], %1;" :: "r"(a), "r"(c) : "memory")

#define MBAR_WAIT(mbar, par) do {                                              \
    uint32_t _m = (mbar), _p = (par), _d;                                      \
    asm volatile("{ .reg .pred p;"                                             \
        " mbarrier.try_wait.parity.acquire.cta.shared::cta.b64 p, [%1], %2;"   \
        " selp.b32 %0, 1, 0, p; }" : "=r"(_d) : "r"(_m), "r"(_p) : "memory");  \
    if (!_d) {                                                                 \
        asm volatile("{ .reg .pred P1;"                                        \
        " W%=: mbarrier.try_wait.parity.acquire.cta.shared::cta.b64 P1, [%0], %1, 0x989680;" \
        " @P1 bra.uni D%=; bra.uni W%=; D%=: }" :: "r"(_m), "r"(_p) : "memory"); } \
} while (0)

#define MBAR_ARRIVE(mbar) \
    asm volatile("mbarrier.arrive.shared.b64 _, [%0];" :: "r"(mbar) : "memory")

#define MBAR_EXPECT(mbar, bytes) \
    asm volatile("mbarrier.arrive.expect_tx.shared.b64 _, [%0], %1;" :: "r"(mbar), "r"(bytes) : "memory")

#define BULK_G2S(dst, src, bytes, mbar) \
    asm volatile("cp.async.bulk.shared::cluster.global.mbarrier::complete_tx::bytes [%0], [%1], %2, [%3];" \
                 :: "r"(dst), "l"(src), "r"(bytes), "r"(mbar) : "memory")

__device__ __forceinline__ void ldsm4(uint32_t& r0, uint32_t& r1, uint32_t& r2,
                                      uint32_t& r3, uint32_t addr) {
    asm volatile("ldmatrix.sync.aligned.m8n8.x4.shared.b16 {%0,%1,%2,%3}, [%4];"
                 : "=r"(r0), "=r"(r1), "=r"(r2), "=r"(r3) : "r"(addr));
}
// fp32-accumulate HMMA (hi pass)
__device__ __forceinline__ void mma16816(float& d0, float& d1, float& d2, float& d3,
                                         uint32_t a0, uint32_t a1, uint32_t a2, uint32_t a3,
                                         uint32_t b0, uint32_t b1) {
    asm volatile("mma.sync.aligned.m16n8k16.row.col.f32.f16.f16.f32 "
                 "{%0,%1,%2,%3}, {%4,%5,%6,%7}, {%8,%9}, {%0,%1,%2,%3};"
                 : "+f"(d0), "+f"(d1), "+f"(d2), "+f"(d3)
                 : "r"(a0), "r"(a1), "r"(a2), "r"(a3), "r"(b0), "r"(b1));
}
// fp16-accumulate HMMA (lo pass; contributes ~2^-12 of D)
__device__ __forceinline__ void mma16816h(uint32_t& c0, uint32_t& c1,
                                          uint32_t a0, uint32_t a1, uint32_t a2, uint32_t a3,
                                          uint32_t b0, uint32_t b1) {
    asm volatile("mma.sync.aligned.m16n8k16.row.col.f16.f16.f16.f16 "
                 "{%0,%1}, {%2,%3,%4,%5}, {%6,%7}, {%0,%1};"
                 : "+r"(c0), "+r"(c1)
                 : "r"(a0), "r"(a1), "r"(a2), "r"(a3), "r"(b0), "r"(b1));
}

// ---------------------------------------------------------------------------
// Diffusion GEMM. A2 tiled [64 kt][128r][256B], B2 tiled [32 nb][64 kt][128r][128B]
// grid = (32 nb, 8 split), 256 threads, 8 warps (4m x 2n), warp tile 32x64.
// ---------------------------------------------------------------------------
__global__ __launch_bounds__(256, 2)
void gemm_tc(const __half* __restrict__ A2,
             const __half* __restrict__ B2,
             float* __restrict__ part)
{
    extern __shared__ __align__(16) char smem[];
    const uint32_t sb  = smem_u32(smem);
    const uint32_t st0 = sb + 64;

    const int tid  = threadIdx.x;
    const int wid  = tid >> 5, lane = tid & 31;
    const int wm   = wid >> 1;            // 0..3 -> m offset wm*32
    const int wn   = wid & 1;             // 0..1 -> n offset wn*64
    const int nb   = blockIdx.x;
    const int n0   = nb * NT;
    const int split = blockIdx.y;

    if (tid == 0) {
        MBAR_INIT(sb + 0, 1);  MBAR_INIT(sb + 8, 1);
        MBAR_INIT(sb + 16, 8); MBAR_INIT(sb + 24, 8);
    }
    __syncthreads();

    const __half* Asrc = A2 + (size_t)(split * NKT) * ATILE_H;
    const __half* Bsrc = B2 + (size_t)(nb * NKTOT + split * NKT) * BTILE_H;

    auto issue_load = [&](int tt) {       // thread 0 only
        const uint32_t s    = (uint32_t)(tt & 1);
        const uint32_t mbar = sb + s * 8;
        const uint32_t dst  = st0 + s * STAGESZ;
        MBAR_EXPECT(mbar, 49152u);
        BULK_G2S(dst,          Asrc + (size_t)tt * ATILE_H, 32768u, mbar);
        BULK_G2S(dst + 32768u, Bsrc + (size_t)tt * BTILE_H, 16384u, mbar);
    };

    if (tid == 0) { issue_load(0); issue_load(1); }

    // ---- ldsm row bases (bytes within a stage) ----
    const int r8  = lane & 7;
    const int seg = lane >> 3;            // 0..3
    const int sak = seg >> 1;             // A: k8 selector
    const int sam = seg & 1;              // A: m8 selector
    const int sbn = seg >> 1;             // B: n8 selector
    const int sbk = seg & 1;              // B: k8 selector
    uint32_t baseA[2];
#pragma unroll
    for (int mt = 0; mt < 2; mt++)
        baseA[mt] = (uint32_t)((wm * 32 + mt * 16 + sam * 8 + r8) * 256);
    uint32_t baseB[4];
#pragma unroll
    for (int p = 0; p < 4; p++)
        baseB[p] = (uint32_t)(32768 + (wn * 64 + p * 16 + sbn * 8 + r8) * 128);

    float    accF[2][8][4] = {};
    uint32_t accH[2][8][2] = {};          // fp16x2 pairs, init +0

#pragma unroll 1
    for (int tt = 0; tt < NKT; tt++) {
        const uint32_t s   = (uint32_t)(tt & 1);
        const uint32_t par = (uint32_t)((tt >> 1) & 1);
        MBAR_WAIT(sb + s * 8, par);       // full[s]

        const uint32_t st = st0 + s * STAGESZ;

#pragma unroll
        for (int ks = 0; ks < 4; ks++) {
            const uint32_t offA = (uint32_t)(((ks * 2 + sak) ^ r8) << 4);
            const uint32_t offB = (uint32_t)(((ks * 2 + sbk) ^ r8) << 4);
            uint32_t ah[2][4], al[2][4];
#pragma unroll
            for (int mt = 0; mt < 2; mt++) {
                const uint32_t a = st + baseA[mt] + offA;
                ldsm4(ah[mt][0], ah[mt][1], ah[mt][2], ah[mt][3], a);
                ldsm4(al[mt][0], al[mt][1], al[mt][2], al[mt][3], a + 128);
            }
            uint32_t bh[8][2];
#pragma unroll
            for (int p = 0; p < 4; p++) {
                const uint32_t b = st + baseB[p] + offB;
                ldsm4(bh[2*p][0], bh[2*p][1], bh[2*p+1][0], bh[2*p+1][1], b);
            }
            // pass 1: hi*hi, fp32 accum
#pragma unroll
            for (int mt = 0; mt < 2; mt++)
#pragma unroll
                for (int nt = 0; nt < 8; nt++)
                    mma16816(accF[mt][nt][0], accF[mt][nt][1], accF[mt][nt][2], accF[mt][nt][3],
                             ah[mt][0], ah[mt][1], ah[mt][2], ah[mt][3],
                             bh[nt][0], bh[nt][1]);
            // pass 2: lo*hi, fp16 accum (tiny correction term)
#pragma unroll
            for (int mt = 0; mt < 2; mt++)
#pragma unroll
                for (int nt = 0; nt < 8; nt++)
                    mma16816h(accH[mt][nt][0], accH[mt][nt][1],
                              al[mt][0], al[mt][1], al[mt][2], al[mt][3],
                              bh[nt][0], bh[nt][1]);
        }

        if (lane == 0) MBAR_ARRIVE(sb + 16 + s * 8);      // release stage s

        if (tid == 0 && tt + 2 < NKT) {
            MBAR_WAIT(sb + 16 + s * 8, par);              // empty[s]
            issue_load(tt + 2);
        }
    }

    // ---- epilogue: merge fp32 + fp16 accum, write part ----
    const int mrow = lane >> 2;           // 0..7
    const int ncol = (lane & 3) * 2;      // 0,2,4,6
#pragma unroll
    for (int mt = 0; mt < 2; mt++) {
#pragma unroll
        for (int nt = 0; nt < 8; nt++) {
            const int c = wm * 32 + mt * 16 + mrow;
            const int n = n0 + wn * 64 + nt * 8 + ncol;
            float2 l0 = __half22float2(*reinterpret_cast<__half2*>(&accH[mt][nt][0]));
            float2 l1 = __half22float2(*reinterpret_cast<__half2*>(&accH[mt][nt][1]));
            float* d0 = part + ((size_t)(split * CC + c)) * NNODES + n;
            float* d1 = part + ((size_t)(split * CC + c + 8)) * NNODES + n;
            *reinterpret_cast<float2*>(d0) =
                make_float2(accF[mt][nt][0] + l0.x, accF[mt][nt][1] + l0.y);
            *reinterpret_cast<float2*>(d1) =
                make_float2(accF[mt][nt][2] + l1.x, accF[mt][nt][3] + l1.y);
        }
    }
}

// ---------------------------------------------------------------------------
// fp32 -> fp16 hi/lo split helper
// ---------------------------------------------------------------------------
__device__ __forceinline__ void split4h(float4 a, uint2& H, uint2& L) {
    __half h0 = __float2half_rn(a.x), h1 = __float2half_rn(a.y);
    __half h2 = __float2half_rn(a.z), h3 = __float2half_rn(a.w);
    __half l0 = __float2half_rn(a.x - __half2float(h0));
    __half l1 = __float2half_rn(a.y - __half2float(h1));
    __half l2 = __float2half_rn(a.z - __half2float(h2));
    __half l3 = __float2half_rn(a.w - __half2float(h3));
    H.x = ((uint32_t)__half_as_ushort(h1) << 16) | __half_as_ushort(h0);
    H.y = ((uint32_t)__half_as_ushort(h3) << 16) | __half_as_ushort(h2);
    L.x = ((uint32_t)__half_as_ushort(l1) << 16) | __half_as_ushort(l0);
    L.y = ((uint32_t)__half_as_ushort(l3) << 16) | __half_as_ushort(l2);
}

// S: fp32 [4096][4096] -> fp16 hi-only, tiled+swizzled B layout (NT=128)
__global__ __launch_bounds__(256)
void cvtS(const float4* __restrict__ in, __half* __restrict__ out, int n4)
{
    int i = blockIdx.x * 256 + threadIdx.x;
    if (i >= n4) return;
    float4 a = in[i];
    __half h0 = __float2half_rn(a.x), h1 = __float2half_rn(a.y);
    __half h2 = __float2half_rn(a.z), h3 = __float2half_rn(a.w);
    uint2 H;
    H.x = ((uint32_t)__half_as_ushort(h1) << 16) | __half_as_ushort(h0);
    H.y = ((uint32_t)__half_as_ushort(h3) << 16) | __half_as_ushort(h2);
    const int e  = i * 4;
    const int n  = e >> 12, k = e & 4095;
    const int nb = n >> 7,  r = n & 127;
    const int kt = k >> 6,  c = (k & 63) >> 3;
    const size_t base = (size_t)(nb * NKTOT + kt) * BTILE_H
                      + r * 64 + ((c ^ (r & 7)) << 3) + (k & 7);
    *reinterpret_cast<uint2*>(out + base) = H;
}

// A-type index: tiled+swizzled A layout
__device__ __forceinline__ size_t a2_index(int row, int k) {
    const int kt = k >> 6, c = (k & 63) >> 3;
    return (size_t)kt * ATILE_H + row * 128 + ((c ^ (row & 7)) << 3) + (k & 7);
}

__global__ __launch_bounds__(256)
void cvtA(const float4* __restrict__ in, __half* __restrict__ out, int n4)
{
    int i = blockIdx.x * 256 + threadIdx.x;
    if (i >= n4) return;
    uint2 H, L;
    split4h(in[i], H, L);
    const int e   = i * 4;
    const int row = e >> 12, k = e & 4095;
    const size_t base = a2_index(row, k);
    *reinterpret_cast<uint2*>(out + base)      = H;
    *reinterpret_cast<uint2*>(out + base + 64) = L;
}

// ---------------------------------------------------------------------------
// split-K reduce + epilogue. MODE 0: Y = sum; 1: Y = sum + V; 2: relu(sum+V+b)
// ---------------------------------------------------------------------------
template <int MODE>
__global__ __launch_bounds__(256)
void reduce_splitk(const float* __restrict__ part, const float* __restrict__ V,
                   const float* __restrict__ bias, float* __restrict__ Yf,
                   __half* __restrict__ Y2)
{
    const int i = blockIdx.x * 256 + threadIdx.x;          // float4 index
    const float4* p = reinterpret_cast<const float4*>(part);
    const int STR = CC * NNODES / 4;
    float4 a = p[i];
#pragma unroll
    for (int s = 1; s < SPLITK; s++) {
        float4 q = p[i + s * STR];
        a.x += q.x; a.y += q.y; a.z += q.z; a.w += q.w;
    }
    if (MODE >= 1) {
        float4 v = reinterpret_cast<const float4*>(V)[i];
        a.x += v.x; a.y += v.y; a.z += v.z; a.w += v.w;
    }
    const int e  = i * 4;
    const int ch = e >> 12;                                // 0..127
    if (MODE == 2) {
        const float bv = bias[ch & 15];
        a.x = fmaxf(a.x + bv, 0.f); a.y = fmaxf(a.y + bv, 0.f);
        a.z = fmaxf(a.z + bv, 0.f); a.w = fmaxf(a.w + bv, 0.f);
    }
    if (Yf) reinterpret_cast<float4*>(Yf)[i] = a;
    if (Y2) {
        uint2 H, L;
        split4h(a, H, L);
        const size_t base = a2_index(ch, e & 4095);
        *reinterpret_cast<uint2*>(Y2 + base)      = H;
        *reinterpret_cast<uint2*>(Y2 + base + 64) = L;
    }
}

// ---------------------------------------------------------------------------
// Fused 16->32 layer head: z2 = split-K sum of part (inline), then
// y[g] = relu(ba[g] + sum_k sum_f Wa[g,k,f] z_k)   (y32 never materialized)
// then projections of the NEXT layer: v_k[g] = sum_f Wb[g,k,f] * y[f]
// (k=0,1 -> fp32 v0/v1 ; k=2 -> tiled fp16 hi/lo v2c).
// Wa: [32][3][16], Wb: [16][3][32]. grid (16, 8), 256 threads.
// ---------------------------------------------------------------------------
__global__ __launch_bounds__(256)
void layer_fused(const float* __restrict__ part, const float* __restrict__ z1f,
                 const float* __restrict__ z0, const float* __restrict__ Wa,
                 const float* __restrict__ ba, const float* __restrict__ Wb,
                 float* __restrict__ v0, float* __restrict__ v1,
                 __half* __restrict__ v2c)
{
    __shared__ float Ws [32 * 48];
    __shared__ float Ws2[16 * 96];
    __shared__ float bs [32];
    const int tid = threadIdx.x;
    for (int i = tid; i < 32 * 48; i += 256) Ws[i]  = Wa[i];
    for (int i = tid; i < 16 * 96; i += 256) Ws2[i] = Wb[i];
    if (tid < 32) bs[tid] = ba[tid];
    __syncthreads();

    const int n = blockIdx.x * 256 + tid;
    const int b = blockIdx.y;

    float y[32];
#pragma unroll
    for (int g = 0; g < 32; g++) y[g] = bs[g];

#pragma unroll
    for (int f = 0; f < 16; f++) {                          // tap 0: z0
        float zv = z0[((size_t)(b * 16 + f)) * NNODES + n];
#pragma unroll
        for (int g = 0; g < 32; g++) y[g] += Ws[g * 48 + f] * zv;
    }
#pragma unroll
    for (int f = 0; f < 16; f++) {                          // tap 1: z1f
        float zv = z1f[((size_t)(b * 16 + f)) * NNODES + n];
#pragma unroll
        for (int g = 0; g < 32; g++) y[g] += Ws[g * 48 + 16 + f] * zv;
    }
#pragma unroll
    for (int f = 0; f < 16; f++) {                          // tap 2: sum(part)
        float zv = 0.f;
#pragma unroll
        for (int s = 0; s < SPLITK; s++)
            zv += part[((size_t)(s * CC + b * 16 + f)) * NNODES + n];
#pragma unroll
        for (int g = 0; g < 32; g++) y[g] += Ws[g * 48 + 32 + f] * zv;
    }
#pragma unroll
    for (int g = 0; g < 32; g++) y[g] = fmaxf(y[g], 0.f);

    // projections for the following 32->16 layer
#pragma unroll
    for (int g = 0; g < 16; g++) {
        float a0 = 0.f, a1 = 0.f, a2 = 0.f;
#pragma unroll
        for (int f = 0; f < 32; f++) {
            const float yv = y[f];
            a0 += Ws2[g * 96 +       f] * yv;
            a1 += Ws2[g * 96 + 32 +  f] * yv;
            a2 += Ws2[g * 96 + 64 +  f] * yv;
        }
        v0[((size_t)(b * 16 + g)) * NNODES + n] = a0;
        v1[((size_t)(b * 16 + g)) * NNODES + n] = a1;
        const size_t o = a2_index(b * 16 + g, n);
        __half h = __float2half_rn(a2);
        v2c[o]      = h;
        v2c[o + 64] = __float2half_rn(a2 - __half2float(h));
    }
}

// ---------------------------------------------------------------------------
// MLP head
// ---------------------------------------------------------------------------
__global__ __launch_bounds__(256)
void mlp1b(const float* __restrict__ y, const float* __restrict__ W1,
           float* __restrict__ hp)
{
    const int jg = blockIdx.x;    // 8 groups of 8 outputs
    const int ks = blockIdx.y;    // 8 k-slices of 2048 float4
    const float4* Y4 = reinterpret_cast<const float4*>(y);
    const float4* W4 = reinterpret_cast<const float4*>(W1);

    float s[8][8] = {};           // [jj][b]
    for (int i = threadIdx.x; i < 2048; i += 256) {
        const int off = ks * 2048 + i;
        float4 yv[8];
#pragma unroll
        for (int b = 0; b < 8; b++) yv[b] = Y4[(size_t)b * 16384 + off];
#pragma unroll
        for (int jj = 0; jj < 8; jj++) {
            float4 w = W4[(size_t)(jg * 8 + jj) * 16384 + off];
#pragma unroll
            for (int b = 0; b < 8; b++)
                s[jj][b] += yv[b].x * w.x + yv[b].y * w.y + yv[b].z * w.z + yv[b].w * w.w;
        }
    }
    __shared__ float red[8][64];  // [warp][jj*8+b]
    const int wid = threadIdx.x >> 5, lane = threadIdx.x & 31;
#pragma unroll
    for (int jj = 0; jj < 8; jj++)
#pragma unroll
        for (int b = 0; b < 8; b++) {
            float v = s[jj][b];
#pragma unroll
            for (int o = 16; o > 0; o >>= 1) v += __shfl_down_sync(0xffffffffu, v, o);
            if (lane == 0) red[wid][jj * 8 + b] = v;
        }
    __syncthreads();
    if (threadIdx.x < 64) {
        const int jj = threadIdx.x >> 3, b = threadIdx.x & 7;
        float t = 0.f;
#pragma unroll
        for (int w = 0; w < 8; w++) t += red[w][jj * 8 + b];
        hp[((size_t)ks * 8 + b) * 64 + jg * 8 + jj] = t;
    }
}

__global__ __launch_bounds__(64)
void mlp2b(const float* __restrict__ hp, const float* __restrict__ b1,
           const float* __restrict__ W2, const float* __restrict__ b2,
           float* __restrict__ out)
{
    const int b = blockIdx.x, j = threadIdx.x;
    float hv = b1[j];
#pragma unroll
    for (int s = 0; s < 8; s++) hv += hp[((size_t)s * 8 + b) * 64 + j];
    float v = fmaxf(hv, 0.f) * W2[j];
#pragma unroll
    for (int o = 16; o > 0; o >>= 1) v += __shfl_down_sync(0xffffffffu, v, o);
    __shared__ float s2[2];
    if ((j & 31) == 0) s2[j >> 5] = v;
    __syncthreads();
    if (j == 0) out[b] = s2[0] + s2[1] + b2[0];
}

// ---------------------------------------------------------------------------
extern "C" void kernel_launch(void* const* d_in, const int* in_sizes, int n_in,
                              void* d_out, int out_size)
{
    const float* x   = (const float*)d_in[0];
    const float* Sc  = (const float*)d_in[1];
    const float* Sl  = (const float*)d_in[2];
    const float* Wc1 = (const float*)d_in[3];
    const float* bc1 = (const float*)d_in[4];
    const float* Wc2 = (const float*)d_in[5];
    const float* bc2 = (const float*)d_in[6];
    const float* Wl1 = (const float*)d_in[7];
    const float* bl1 = (const float*)d_in[8];
    const float* Wl2 = (const float*)d_in[9];
    const float* bl2 = (const float*)d_in[10];
    const float* Wm1 = (const float*)d_in[11];
    const float* bm1 = (const float*)d_in[12];
    const float* Wm2 = (const float*)d_in[13];
    const float* bm2 = (const float*)d_in[14];
    float* out = (float*)d_out;

    cudaFuncSetAttribute(gemm_tc, cudaFuncAttributeMaxDynamicSharedMemorySize, SMEMSZ);

    __half *Sc2, *Sl2, *x2, *a2, *b2;
    float *part, *z1f, *v0, *v1, *y16, *hp;
    cudaGetSymbolAddress((void**)&Sc2, g_Sc2); cudaGetSymbolAddress((void**)&Sl2, g_Sl2);
    cudaGetSymbolAddress((void**)&x2, g_x2);
    cudaGetSymbolAddress((void**)&a2, g_a2);   cudaGetSymbolAddress((void**)&b2, g_b2);
    cudaGetSymbolAddress((void**)&part, g_part);
    cudaGetSymbolAddress((void**)&z1f, g_z1f);
    cudaGetSymbolAddress((void**)&v0, g_v0);   cudaGetSymbolAddress((void**)&v1, g_v1);
    cudaGetSymbolAddress((void**)&y16, g_y16);
    cudaGetSymbolAddress((void**)&hp, g_hp);

    const int SN4 = NNODES * NNODES / 4;          // 4M float4
    const int XN4 = CC * NNODES / 4;              // 128K float4
    cvtS<<<SN4 / 256, 256>>>((const float4*)Sc, Sc2, SN4);
    cvtS<<<SN4 / 256, 256>>>((const float4*)Sl, Sl2, SN4);
    cvtA<<<XN4 / 256, 256>>>((const float4*)x,  x2,  XN4);

    const dim3 gG(NNODES / NT, SPLITK);           // 32 x 8 = 256 CTAs
    const dim3 gR(CC * NNODES / 4 / 256);         // 512 blocks
    const dim3 gF(NNODES / 256, BATCH);           // 16 x 8 fused head

    // ---- Layer 1 (clique, 16 -> 32) + Layer-2 projections, fused ----
    gemm_tc<<<gG, 256, SMEMSZ>>>(x2, Sc2, part);
    reduce_splitk<0><<<gR, 256>>>(part, nullptr, nullptr, z1f, a2);
    gemm_tc<<<gG, 256, SMEMSZ>>>(a2, Sc2, part);
    layer_fused<<<gF, 256>>>(part, z1f, x, Wc1, bc1, Wc2, v0, v1, b2);

    // ---- Layer 2 (clique, 32 -> 16): Horner ----
    gemm_tc<<<gG, 256, SMEMSZ>>>(b2, Sc2, part);
    reduce_splitk<1><<<gR, 256>>>(part, v1, nullptr, nullptr, a2);
    gemm_tc<<<gG, 256, SMEMSZ>>>(a2, Sc2, part);
    reduce_splitk<2><<<gR, 256>>>(part, v0, bc2, y16, b2);

    // ---- Layer 3 (line, 16 -> 32) + Layer-4 projections, fused ----
    gemm_tc<<<gG, 256, SMEMSZ>>>(b2, Sl2, part);
    reduce_splitk<0><<<gR, 256>>>(part, nullptr, nullptr, z1f, a2);
    gemm_tc<<<gG, 256, SMEMSZ>>>(a2, Sl2, part);
    layer_fused<<<gF, 256>>>(part, z1f, y16, Wl1, bl1, Wl2, v0, v1, b2);

    // ---- Layer 4 (line, 32 -> 16): Horner ----
    gemm_tc<<<gG, 256, SMEMSZ>>>(b2, Sl2, part);
    reduce_splitk<1><<<gR, 256>>>(part, v1, nullptr, nullptr, a2);
    gemm_tc<<<gG, 256, SMEMSZ>>>(a2, Sl2, part);
    reduce_splitk<2><<<gR, 256>>>(part, v0, bl2, y16, nullptr);

    // ---- MLP head ----
    mlp1b<<<dim3(8, 8), 256>>>(y16, Wm1, hp);
    mlp2b<<<BATCH, 64>>>(hp, bm1, Wm2, bm2, out);
}

// round 12
// speedup vs baseline: 1.1465x; 1.1465x over previous
#include <cuda_runtime.h>
#include <cuda_fp16.h>
#include <cstdint>

// ---------------------------------------------------------------------------
// SelectionGNN (clique+line), B=8, N=4096, E=1, K=3, F=[16,32,16]
// Diffusion GEMMs (8x: 128x4096x4096) via mma.sync fp16 2-pass:
//   D = Ah*Bh + Al*Bh  (A fp16 hi/lo split, B = fp16(S) hi only),
//   BOTH passes fp32 accumulation (R11 showed f16-accum is NOT faster here).
// Operands PRE-TILED + PRE-SWIZZLED in gmem, TMA bulk loads, full/empty
// mbarrier pipeline, 2 CTAs/SM. 16->32 layers fused (split-K sum + combine +
// next-layer projections in one kernel; y32 never materialized).
// R12 = R10 gemm (25.1us measured) + R11 fusion (66us non-gemm measured).
// ---------------------------------------------------------------------------

#define NNODES 4096
#define BATCH  8
#define CC     128                 // channels = B*16 (GEMM M)
#define NT     128                 // n-tile per CTA
#define SPLITK 8
#define KC     (NNODES / SPLITK)   // 512 k per CTA
#define NKT    (KC / 64)           // 8 k-tiles (64 k each)
#define NKTOT  (NNODES / 64)       // 64 k-tiles total

#define ATILE_H  16384             // A tile halves (32KB): 128 rows x 256B
#define BTILE_H  8192              // B tile halves (16KB): 128 rows x 128B
#define STAGESZ  49152             // bytes: A(32K) + B(16K)
#define NSTAGE   2
#define SMEMSZ   (64 + NSTAGE * STAGESZ)   // 98368 -> 2 CTAs/SM fit

// ---------------- scratch (device globals; allocation is forbidden) --------
__device__ __align__(256) __half g_Sc2[(size_t)NNODES * NNODES];   // 32MB tiled
__device__ __align__(256) __half g_Sl2[(size_t)NNODES * NNODES];   // 32MB tiled
__device__ __align__(256) __half g_x2 [NKTOT * ATILE_H];           // 2MB tiled
__device__ __align__(256) __half g_a2 [NKTOT * ATILE_H];
__device__ __align__(256) __half g_b2 [NKTOT * ATILE_H];
__device__ __align__(256) float g_part[SPLITK * CC * NNODES];      // 16.8 MB
__device__ __align__(256) float g_z1f [CC * NNODES];
__device__ __align__(256) float g_v0  [CC * NNODES];
__device__ __align__(256) float g_v1  [CC * NNODES];
__device__ __align__(256) float g_y16 [CC * NNODES];
__device__ __align__(256) float g_hp  [8 * BATCH * 64];

// ---------------- PTX helpers (baseline sm_90-level PTX only) ---------------
__device__ __forceinline__ uint32_t smem_u32(const void* p) {
    uint32_t a;
    asm("{ .reg .u64 t; cvta.to.shared.u64 t, %1; cvt.u32.u64 %0, t; }" : "=r"(a) : "l"(p));
    return a;
}
#define MBAR_INIT(a, c) asm volatile("mbarrier.init.shared.b64 [%0], %1;" :: "r"(a), "r"(c) : "memory")

#define MBAR_WAIT(mbar, par) do {                                              \
    uint32_t _m = (mbar), _p = (par), _d;                                      \
    asm volatile("{ .reg .pred p;"                                             \
        " mbarrier.try_wait.parity.acquire.cta.shared::cta.b64 p, [%1], %2;"   \
        " selp.b32 %0, 1, 0, p; }" : "=r"(_d) : "r"(_m), "r"(_p) : "memory");  \
    if (!_d) {                                                                 \
        asm volatile("{ .reg .pred P1;"                                        \
        " W%=: mbarrier.try_wait.parity.acquire.cta.shared::cta.b64 P1, [%0], %1, 0x989680;" \
        " @P1 bra.uni D%=; bra.uni W%=; D%=: }" :: "r"(_m), "r"(_p) : "memory"); } \
} while (0)

#define MBAR_ARRIVE(mbar) \
    asm volatile("mbarrier.arrive.shared.b64 _, [%0];" :: "r"(mbar) : "memory")

#define MBAR_EXPECT(mbar, bytes) \
    asm volatile("mbarrier.arrive.expect_tx.shared.b64 _, [%0], %1;" :: "r"(mbar), "r"(bytes) : "memory")

#define BULK_G2S(dst, src, bytes, mbar) \
    asm volatile("cp.async.bulk.shared::cluster.global.mbarrier::complete_tx::bytes [%0], [%1], %2, [%3];" \
                 :: "r"(dst), "l"(src), "r"(bytes), "r"(mbar) : "memory")

__device__ __forceinline__ void ldsm4(uint32_t& r0, uint32_t& r1, uint32_t& r2,
                                      uint32_t& r3, uint32_t addr) {
    asm volatile("ldmatrix.sync.aligned.m8n8.x4.shared.b16 {%0,%1,%2,%3}, [%4];"
                 : "=r"(r0), "=r"(r1), "=r"(r2), "=r"(r3) : "r"(addr));
}
__device__ __forceinline__ void mma16816(float& d0, float& d1, float& d2, float& d3,
                                         uint32_t a0, uint32_t a1, uint32_t a2, uint32_t a3,
                                         uint32_t b0, uint32_t b1) {
    asm volatile("mma.sync.aligned.m16n8k16.row.col.f32.f16.f16.f32 "
                 "{%0,%1,%2,%3}, {%4,%5,%6,%7}, {%8,%9}, {%0,%1,%2,%3};"
                 : "+f"(d0), "+f"(d1), "+f"(d2), "+f"(d3)
                 : "r"(a0), "r"(a1), "r"(a2), "r"(a3), "r"(b0), "r"(b1));
}

// ---------------------------------------------------------------------------
// Diffusion GEMM (R10 version, verbatim). A2 tiled [64 kt][128r][256B],
// B2 tiled [32 nb][64 kt][128r][128B]. grid = (32 nb, 8 split), 256 threads,
// 8 warps (4m x 2n), warp tile 32x64, 2 CTAs/SM.
// ---------------------------------------------------------------------------
__global__ __launch_bounds__(256, 2)
void gemm_tc(const __half* __restrict__ A2,
             const __half* __restrict__ B2,
             float* __restrict__ part)
{
    extern __shared__ __align__(16) char smem[];
    const uint32_t sb  = smem_u32(smem);
    const uint32_t st0 = sb + 64;

    const int tid  = threadIdx.x;
    const int wid  = tid >> 5, lane = tid & 31;
    const int wm   = wid >> 1;            // 0..3 -> m offset wm*32
    const int wn   = wid & 1;             // 0..1 -> n offset wn*64
    const int nb   = blockIdx.x;
    const int n0   = nb * NT;
    const int split = blockIdx.y;

    if (tid == 0) {
        MBAR_INIT(sb + 0, 1);  MBAR_INIT(sb + 8, 1);
        MBAR_INIT(sb + 16, 8); MBAR_INIT(sb + 24, 8);
    }
    __syncthreads();

    const __half* Asrc = A2 + (size_t)(split * NKT) * ATILE_H;
    const __half* Bsrc = B2 + (size_t)(nb * NKTOT + split * NKT) * BTILE_H;

    auto issue_load = [&](int tt) {       // thread 0 only
        const uint32_t s    = (uint32_t)(tt & 1);
        const uint32_t mbar = sb + s * 8;
        const uint32_t dst  = st0 + s * STAGESZ;
        MBAR_EXPECT(mbar, 49152u);
        BULK_G2S(dst,          Asrc + (size_t)tt * ATILE_H, 32768u, mbar);
        BULK_G2S(dst + 32768u, Bsrc + (size_t)tt * BTILE_H, 16384u, mbar);
    };

    if (tid == 0) { issue_load(0); issue_load(1); }

    // ---- ldsm row bases (bytes within a stage) ----
    const int r8  = lane & 7;
    const int seg = lane >> 3;            // 0..3
    const int sak = seg >> 1;             // A: k8 selector
    const int sam = seg & 1;              // A: m8 selector
    const int sbn = seg >> 1;             // B: n8 selector
    const int sbk = seg & 1;              // B: k8 selector
    uint32_t baseA[2];
#pragma unroll
    for (int mt = 0; mt < 2; mt++)
        baseA[mt] = (uint32_t)((wm * 32 + mt * 16 + sam * 8 + r8) * 256);
    uint32_t baseB[4];
#pragma unroll
    for (int p = 0; p < 4; p++)
        baseB[p] = (uint32_t)(32768 + (wn * 64 + p * 16 + sbn * 8 + r8) * 128);

    float acc[2][8][4] = {};

#pragma unroll 1
    for (int tt = 0; tt < NKT; tt++) {
        const uint32_t s   = (uint32_t)(tt & 1);
        const uint32_t par = (uint32_t)((tt >> 1) & 1);
        MBAR_WAIT(sb + s * 8, par);       // full[s]

        const uint32_t st = st0 + s * STAGESZ;

#pragma unroll
        for (int ks = 0; ks < 4; ks++) {
            const uint32_t offA = (uint32_t)(((ks * 2 + sak) ^ r8) << 4);
            const uint32_t offB = (uint32_t)(((ks * 2 + sbk) ^ r8) << 4);
            uint32_t ah[2][4], al[2][4];
#pragma unroll
            for (int mt = 0; mt < 2; mt++) {
                const uint32_t a = st + baseA[mt] + offA;
                ldsm4(ah[mt][0], ah[mt][1], ah[mt][2], ah[mt][3], a);
                ldsm4(al[mt][0], al[mt][1], al[mt][2], al[mt][3], a + 128);
            }
            uint32_t bh[8][2];
#pragma unroll
            for (int p = 0; p < 4; p++) {
                const uint32_t b = st + baseB[p] + offB;
                ldsm4(bh[2*p][0], bh[2*p][1], bh[2*p+1][0], bh[2*p+1][1], b);
            }
            // pass 1: hi*hi
#pragma unroll
            for (int mt = 0; mt < 2; mt++)
#pragma unroll
                for (int nt = 0; nt < 8; nt++)
                    mma16816(acc[mt][nt][0], acc[mt][nt][1], acc[mt][nt][2], acc[mt][nt][3],
                             ah[mt][0], ah[mt][1], ah[mt][2], ah[mt][3],
                             bh[nt][0], bh[nt][1]);
            // pass 2: lo*hi
#pragma unroll
            for (int mt = 0; mt < 2; mt++)
#pragma unroll
                for (int nt = 0; nt < 8; nt++)
                    mma16816(acc[mt][nt][0], acc[mt][nt][1], acc[mt][nt][2], acc[mt][nt][3],
                             al[mt][0], al[mt][1], al[mt][2], al[mt][3],
                             bh[nt][0], bh[nt][1]);
        }

        if (lane == 0) MBAR_ARRIVE(sb + 16 + s * 8);      // release stage s

        if (tid == 0 && tt + 2 < NKT) {
            MBAR_WAIT(sb + 16 + s * 8, par);              // empty[s]
            issue_load(tt + 2);
        }
    }

    // ---- epilogue: D frag -> part[(split*128 + c) * 4096 + n] ----
    const int mrow = lane >> 2;           // 0..7
    const int ncol = (lane & 3) * 2;      // 0,2,4,6
#pragma unroll
    for (int mt = 0; mt < 2; mt++) {
#pragma unroll
        for (int nt = 0; nt < 8; nt++) {
            const int c = wm * 32 + mt * 16 + mrow;
            const int n = n0 + wn * 64 + nt * 8 + ncol;
            float* d0 = part + ((size_t)(split * CC + c)) * NNODES + n;
            float* d1 = part + ((size_t)(split * CC + c + 8)) * NNODES + n;
            *reinterpret_cast<float2*>(d0) = make_float2(acc[mt][nt][0], acc[mt][nt][1]);
            *reinterpret_cast<float2*>(d1) = make_float2(acc[mt][nt][2], acc[mt][nt][3]);
        }
    }
}

// ---------------------------------------------------------------------------
// fp32 -> fp16 hi/lo split helper
// ---------------------------------------------------------------------------
__device__ __forceinline__ void split4h(float4 a, uint2& H, uint2& L) {
    __half h0 = __float2half_rn(a.x), h1 = __float2half_rn(a.y);
    __half h2 = __float2half_rn(a.z), h3 = __float2half_rn(a.w);
    __half l0 = __float2half_rn(a.x - __half2float(h0));
    __half l1 = __float2half_rn(a.y - __half2float(h1));
    __half l2 = __float2half_rn(a.z - __half2float(h2));
    __half l3 = __float2half_rn(a.w - __half2float(h3));
    H.x = ((uint32_t)__half_as_ushort(h1) << 16) | __half_as_ushort(h0);
    H.y = ((uint32_t)__half_as_ushort(h3) << 16) | __half_as_ushort(h2);
    L.x = ((uint32_t)__half_as_ushort(l1) << 16) | __half_as_ushort(l0);
    L.y = ((uint32_t)__half_as_ushort(l3) << 16) | __half_as_ushort(l2);
}

// S: fp32 [4096][4096] -> fp16 hi-only, tiled+swizzled B layout (NT=128)
__global__ __launch_bounds__(256)
void cvtS(const float4* __restrict__ in, __half* __restrict__ out, int n4)
{
    int i = blockIdx.x * 256 + threadIdx.x;
    if (i >= n4) return;
    float4 a = in[i];
    __half h0 = __float2half_rn(a.x), h1 = __float2half_rn(a.y);
    __half h2 = __float2half_rn(a.z), h3 = __float2half_rn(a.w);
    uint2 H;
    H.x = ((uint32_t)__half_as_ushort(h1) << 16) | __half_as_ushort(h0);
    H.y = ((uint32_t)__half_as_ushort(h3) << 16) | __half_as_ushort(h2);
    const int e  = i * 4;
    const int n  = e >> 12, k = e & 4095;
    const int nb = n >> 7,  r = n & 127;
    const int kt = k >> 6,  c = (k & 63) >> 3;
    const size_t base = (size_t)(nb * NKTOT + kt) * BTILE_H
                      + r * 64 + ((c ^ (r & 7)) << 3) + (k & 7);
    *reinterpret_cast<uint2*>(out + base) = H;
}

// A-type index: tiled+swizzled A layout
__device__ __forceinline__ size_t a2_index(int row, int k) {
    const int kt = k >> 6, c = (k & 63) >> 3;
    return (size_t)kt * ATILE_H + row * 128 + ((c ^ (row & 7)) << 3) + (k & 7);
}

__global__ __launch_bounds__(256)
void cvtA(const float4* __restrict__ in, __half* __restrict__ out, int n4)
{
    int i = blockIdx.x * 256 + threadIdx.x;
    if (i >= n4) return;
    uint2 H, L;
    split4h(in[i], H, L);
    const int e   = i * 4;
    const int row = e >> 12, k = e & 4095;
    const size_t base = a2_index(row, k);
    *reinterpret_cast<uint2*>(out + base)      = H;
    *reinterpret_cast<uint2*>(out + base + 64) = L;
}

// ---------------------------------------------------------------------------
// split-K reduce + epilogue. MODE 0: Y = sum; 1: Y = sum + V; 2: relu(sum+V+b)
// ---------------------------------------------------------------------------
template <int MODE>
__global__ __launch_bounds__(256)
void reduce_splitk(const float* __restrict__ part, const float* __restrict__ V,
                   const float* __restrict__ bias, float* __restrict__ Yf,
                   __half* __restrict__ Y2)
{
    const int i = blockIdx.x * 256 + threadIdx.x;          // float4 index
    const float4* p = reinterpret_cast<const float4*>(part);
    const int STR = CC * NNODES / 4;
    float4 a = p[i];
#pragma unroll
    for (int s = 1; s < SPLITK; s++) {
        float4 q = p[i + s * STR];
        a.x += q.x; a.y += q.y; a.z += q.z; a.w += q.w;
    }
    if (MODE >= 1) {
        float4 v = reinterpret_cast<const float4*>(V)[i];
        a.x += v.x; a.y += v.y; a.z += v.z; a.w += v.w;
    }
    const int e  = i * 4;
    const int ch = e >> 12;                                // 0..127
    if (MODE == 2) {
        const float bv = bias[ch & 15];
        a.x = fmaxf(a.x + bv, 0.f); a.y = fmaxf(a.y + bv, 0.f);
        a.z = fmaxf(a.z + bv, 0.f); a.w = fmaxf(a.w + bv, 0.f);
    }
    if (Yf) reinterpret_cast<float4*>(Yf)[i] = a;
    if (Y2) {
        uint2 H, L;
        split4h(a, H, L);
        const size_t base = a2_index(ch, e & 4095);
        *reinterpret_cast<uint2*>(Y2 + base)      = H;
        *reinterpret_cast<uint2*>(Y2 + base + 64) = L;
    }
}

// ---------------------------------------------------------------------------
// Fused 16->32 layer head: z2 = split-K sum of part (inline), then
// y[g] = relu(ba[g] + sum_k sum_f Wa[g,k,f] z_k)   (y32 never materialized)
// then projections of the NEXT layer: v_k[g] = sum_f Wb[g,k,f] * y[f]
// (k=0,1 -> fp32 v0/v1 ; k=2 -> tiled fp16 hi/lo v2c).
// Wa: [32][3][16], Wb: [16][3][32]. grid (16, 8), 256 threads.
// ---------------------------------------------------------------------------
__global__ __launch_bounds__(256)
void layer_fused(const float* __restrict__ part, const float* __restrict__ z1f,
                 const float* __restrict__ z0, const float* __restrict__ Wa,
                 const float* __restrict__ ba, const float* __restrict__ Wb,
                 float* __restrict__ v0, float* __restrict__ v1,
                 __half* __restrict__ v2c)
{
    __shared__ float Ws [32 * 48];
    __shared__ float Ws2[16 * 96];
    __shared__ float bs [32];
    const int tid = threadIdx.x;
    for (int i = tid; i < 32 * 48; i += 256) Ws[i]  = Wa[i];
    for (int i = tid; i < 16 * 96; i += 256) Ws2[i] = Wb[i];
    if (tid < 32) bs[tid] = ba[tid];
    __syncthreads();

    const int n = blockIdx.x * 256 + tid;
    const int b = blockIdx.y;

    float y[32];
#pragma unroll
    for (int g = 0; g < 32; g++) y[g] = bs[g];

#pragma unroll
    for (int f = 0; f < 16; f++) {                          // tap 0: z0
        float zv = z0[((size_t)(b * 16 + f)) * NNODES + n];
#pragma unroll
        for (int g = 0; g < 32; g++) y[g] += Ws[g * 48 + f] * zv;
    }
#pragma unroll
    for (int f = 0; f < 16; f++) {                          // tap 1: z1f
        float zv = z1f[((size_t)(b * 16 + f)) * NNODES + n];
#pragma unroll
        for (int g = 0; g < 32; g++) y[g] += Ws[g * 48 + 16 + f] * zv;
    }
#pragma unroll
    for (int f = 0; f < 16; f++) {                          // tap 2: sum(part)
        float zv = 0.f;
#pragma unroll
        for (int s = 0; s < SPLITK; s++)
            zv += part[((size_t)(s * CC + b * 16 + f)) * NNODES + n];
#pragma unroll
        for (int g = 0; g < 32; g++) y[g] += Ws[g * 48 + 32 + f] * zv;
    }
#pragma unroll
    for (int g = 0; g < 32; g++) y[g] = fmaxf(y[g], 0.f);

    // projections for the following 32->16 layer
#pragma unroll
    for (int g = 0; g < 16; g++) {
        float a0 = 0.f, a1 = 0.f, a2 = 0.f;
#pragma unroll
        for (int f = 0; f < 32; f++) {
            const float yv = y[f];
            a0 += Ws2[g * 96 +       f] * yv;
            a1 += Ws2[g * 96 + 32 +  f] * yv;
            a2 += Ws2[g * 96 + 64 +  f] * yv;
        }
        v0[((size_t)(b * 16 + g)) * NNODES + n] = a0;
        v1[((size_t)(b * 16 + g)) * NNODES + n] = a1;
        const size_t o = a2_index(b * 16 + g, n);
        __half h = __float2half_rn(a2);
        v2c[o]      = h;
        v2c[o + 64] = __float2half_rn(a2 - __half2float(h));
    }
}

// ---------------------------------------------------------------------------
// MLP head
// ---------------------------------------------------------------------------
__global__ __launch_bounds__(256)
void mlp1b(const float* __restrict__ y, const float* __restrict__ W1,
           float* __restrict__ hp)
{
    const int jg = blockIdx.x;    // 8 groups of 8 outputs
    const int ks = blockIdx.y;    // 8 k-slices of 2048 float4
    const float4* Y4 = reinterpret_cast<const float4*>(y);
    const float4* W4 = reinterpret_cast<const float4*>(W1);

    float s[8][8] = {};           // [jj][b]
    for (int i = threadIdx.x; i < 2048; i += 256) {
        const int off = ks * 2048 + i;
        float4 yv[8];
#pragma unroll
        for (int b = 0; b < 8; b++) yv[b] = Y4[(size_t)b * 16384 + off];
#pragma unroll
        for (int jj = 0; jj < 8; jj++) {
            float4 w = W4[(size_t)(jg * 8 + jj) * 16384 + off];
#pragma unroll
            for (int b = 0; b < 8; b++)
                s[jj][b] += yv[b].x * w.x + yv[b].y * w.y + yv[b].z * w.z + yv[b].w * w.w;
        }
    }
    __shared__ float red[8][64];  // [warp][jj*8+b]
    const int wid = threadIdx.x >> 5, lane = threadIdx.x & 31;
#pragma unroll
    for (int jj = 0; jj < 8; jj++)
#pragma unroll
        for (int b = 0; b < 8; b++) {
            float v = s[jj][b];
#pragma unroll
            for (int o = 16; o > 0; o >>= 1) v += __shfl_down_sync(0xffffffffu, v, o);
            if (lane == 0) red[wid][jj * 8 + b] = v;
        }
    __syncthreads();
    if (threadIdx.x < 64) {
        const int jj = threadIdx.x >> 3, b = threadIdx.x & 7;
        float t = 0.f;
#pragma unroll
        for (int w = 0; w < 8; w++) t += red[w][jj * 8 + b];
        hp[((size_t)ks * 8 + b) * 64 + jg * 8 + jj] = t;
    }
}

__global__ __launch_bounds__(64)
void mlp2b(const float* __restrict__ hp, const float* __restrict__ b1,
           const float* __restrict__ W2, const float* __restrict__ b2,
           float* __restrict__ out)
{
    const int b = blockIdx.x, j = threadIdx.x;
    float hv = b1[j];
#pragma unroll
    for (int s = 0; s < 8; s++) hv += hp[((size_t)s * 8 + b) * 64 + j];
    float v = fmaxf(hv, 0.f) * W2[j];
#pragma unroll
    for (int o = 16; o > 0; o >>= 1) v += __shfl_down_sync(0xffffffffu, v, o);
    __shared__ float s2[2];
    if ((j & 31) == 0) s2[j >> 5] = v;
    __syncthreads();
    if (j == 0) out[b] = s2[0] + s2[1] + b2[0];
}

// ---------------------------------------------------------------------------
extern "C" void kernel_launch(void* const* d_in, const int* in_sizes, int n_in,
                              void* d_out, int out_size)
{
    const float* x   = (const float*)d_in[0];
    const float* Sc  = (const float*)d_in[1];
    const float* Sl  = (const float*)d_in[2];
    const float* Wc1 = (const float*)d_in[3];
    const float* bc1 = (const float*)d_in[4];
    const float* Wc2 = (const float*)d_in[5];
    const float* bc2 = (const float*)d_in[6];
    const float* Wl1 = (const float*)d_in[7];
    const float* bl1 = (const float*)d_in[8];
    const float* Wl2 = (const float*)d_in[9];
    const float* bl2 = (const float*)d_in[10];
    const float* Wm1 = (const float*)d_in[11];
    const float* bm1 = (const float*)d_in[12];
    const float* Wm2 = (const float*)d_in[13];
    const float* bm2 = (const float*)d_in[14];
    float* out = (float*)d_out;

    cudaFuncSetAttribute(gemm_tc, cudaFuncAttributeMaxDynamicSharedMemorySize, SMEMSZ);

    __half *Sc2, *Sl2, *x2, *a2, *b2;
    float *part, *z1f, *v0, *v1, *y16, *hp;
    cudaGetSymbolAddress((void**)&Sc2, g_Sc2); cudaGetSymbolAddress((void**)&Sl2, g_Sl2);
    cudaGetSymbolAddress((void**)&x2, g_x2);
    cudaGetSymbolAddress((void**)&a2, g_a2);   cudaGetSymbolAddress((void**)&b2, g_b2);
    cudaGetSymbolAddress((void**)&part, g_part);
    cudaGetSymbolAddress((void**)&z1f, g_z1f);
    cudaGetSymbolAddress((void**)&v0, g_v0);   cudaGetSymbolAddress((void**)&v1, g_v1);
    cudaGetSymbolAddress((void**)&y16, g_y16);
    cudaGetSymbolAddress((void**)&hp, g_hp);

    const int SN4 = NNODES * NNODES / 4;          // 4M float4
    const int XN4 = CC * NNODES / 4;              // 128K float4
    cvtS<<<SN4 / 256, 256>>>((const float4*)Sc, Sc2, SN4);
    cvtS<<<SN4 / 256, 256>>>((const float4*)Sl, Sl2, SN4);
    cvtA<<<XN4 / 256, 256>>>((const float4*)x,  x2,  XN4);

    const dim3 gG(NNODES / NT, SPLITK);           // 32 x 8 = 256 CTAs
    const dim3 gR(CC * NNODES / 4 / 256);         // 512 blocks
    const dim3 gF(NNODES / 256, BATCH);           // 16 x 8 fused head

    // ---- Layer 1 (clique, 16 -> 32) + Layer-2 projections, fused ----
    gemm_tc<<<gG, 256, SMEMSZ>>>(x2, Sc2, part);
    reduce_splitk<0><<<gR, 256>>>(part, nullptr, nullptr, z1f, a2);
    gemm_tc<<<gG, 256, SMEMSZ>>>(a2, Sc2, part);
    layer_fused<<<gF, 256>>>(part, z1f, x, Wc1, bc1, Wc2, v0, v1, b2);

    // ---- Layer 2 (clique, 32 -> 16): Horner ----
    gemm_tc<<<gG, 256, SMEMSZ>>>(b2, Sc2, part);
    reduce_splitk<1><<<gR, 256>>>(part, v1, nullptr, nullptr, a2);
    gemm_tc<<<gG, 256, SMEMSZ>>>(a2, Sc2, part);
    reduce_splitk<2><<<gR, 256>>>(part, v0, bc2, y16, b2);

    // ---- Layer 3 (line, 16 -> 32) + Layer-4 projections, fused ----
    gemm_tc<<<gG, 256, SMEMSZ>>>(b2, Sl2, part);
    reduce_splitk<0><<<gR, 256>>>(part, nullptr, nullptr, z1f, a2);
    gemm_tc<<<gG, 256, SMEMSZ>>>(a2, Sl2, part);
    layer_fused<<<gF, 256>>>(part, z1f, y16, Wl1, bl1, Wl2, v0, v1, b2);

    // ---- Layer 4 (line, 32 -> 16): Horner ----
    gemm_tc<<<gG, 256, SMEMSZ>>>(b2, Sl2, part);
    reduce_splitk<1><<<gR, 256>>>(part, v1, nullptr, nullptr, a2);
    gemm_tc<<<gG, 256, SMEMSZ>>>(a2, Sl2, part);
    reduce_splitk<2><<<gR, 256>>>(part, v0, bl2, y16, nullptr);

    // ---- MLP head ----
    mlp1b<<<dim3(8, 8), 256>>>(y16, Wm1, hp);
    mlp2b<<<BATCH, 64>>>(hp, bm1, Wm2, bm2, out);
}

// round 13
// speedup vs baseline: 1.1574x; 1.0095x over previous
#include <cuda_runtime.h>
#include <cuda_fp16.h>
#include <cstdint>

// ---------------------------------------------------------------------------
// SelectionGNN (clique+line), B=8, N=4096, E=1, K=3, F=[16,32,16]
// Diffusion GEMMs (8x: 128x4096x4096) via mma.sync fp16 2-pass
// (D = Ah*Bh + Al*Bh, fp32 accum both passes; sm_103a mma.sync HMMA floor).
// Operands PRE-TILED + PRE-SWIZZLED in gmem, TMA bulk loads, full/empty
// mbarrier pipeline, 2 CTAs/SM. 16->32 layers fused.
// R13: cvtS/cvtA at 8 elems/thread (16B stores); cvtS(Sl2) forked onto a
// side stream, joined before the line layers (hidden under clique layers).
// ---------------------------------------------------------------------------

#define NNODES 4096
#define BATCH  8
#define CC     128                 // channels = B*16 (GEMM M)
#define NT     128                 // n-tile per CTA
#define SPLITK 8
#define KC     (NNODES / SPLITK)   // 512 k per CTA
#define NKT    (KC / 64)           // 8 k-tiles (64 k each)
#define NKTOT  (NNODES / 64)       // 64 k-tiles total

#define ATILE_H  16384             // A tile halves (32KB): 128 rows x 256B
#define BTILE_H  8192              // B tile halves (16KB): 128 rows x 128B
#define STAGESZ  49152             // bytes: A(32K) + B(16K)
#define NSTAGE   2
#define SMEMSZ   (64 + NSTAGE * STAGESZ)   // 98368 -> 2 CTAs/SM fit

// ---------------- scratch (device globals; allocation is forbidden) --------
__device__ __align__(256) __half g_Sc2[(size_t)NNODES * NNODES];   // 32MB tiled
__device__ __align__(256) __half g_Sl2[(size_t)NNODES * NNODES];   // 32MB tiled
__device__ __align__(256) __half g_x2 [NKTOT * ATILE_H];           // 2MB tiled
__device__ __align__(256) __half g_a2 [NKTOT * ATILE_H];
__device__ __align__(256) __half g_b2 [NKTOT * ATILE_H];
__device__ __align__(256) float g_part[SPLITK * CC * NNODES];      // 16.8 MB
__device__ __align__(256) float g_z1f [CC * NNODES];
__device__ __align__(256) float g_v0  [CC * NNODES];
__device__ __align__(256) float g_v1  [CC * NNODES];
__device__ __align__(256) float g_y16 [CC * NNODES];
__device__ __align__(256) float g_hp  [8 * BATCH * 64];

// ---------------- PTX helpers (baseline sm_90-level PTX only) ---------------
__device__ __forceinline__ uint32_t smem_u32(const void* p) {
    uint32_t a;
    asm("{ .reg .u64 t; cvta.to.shared.u64 t, %1; cvt.u32.u64 %0, t; }" : "=r"(a) : "l"(p));
    return a;
}
#define MBAR_INIT(a, c) asm volatile("mbarrier.init.shared.b64 [%0], %1;" :: "r"(a), "r"(c) : "memory")

#define MBAR_WAIT(mbar, par) do {                                              \
    uint32_t _m = (mbar), _p = (par), _d;                                      \
    asm volatile("{ .reg .pred p;"                                             \
        " mbarrier.try_wait.parity.acquire.cta.shared::cta.b64 p, [%1], %2;"   \
        " selp.b32 %0, 1, 0, p; }" : "=r"(_d) : "r"(_m), "r"(_p) : "memory");  \
    if (!_d) {                                                                 \
        asm volatile("{ .reg .pred P1;"                                        \
        " W%=: mbarrier.try_wait.parity.acquire.cta.shared::cta.b64 P1, [%0], %1, 0x989680;" \
        " @P1 bra.uni D%=; bra.uni W%=; D%=: }" :: "r"(_m), "r"(_p) : "memory"); } \
} while (0)

#define MBAR_ARRIVE(mbar) \
    asm volatile("mbarrier.arrive.shared.b64 _, [%0];" :: "r"(mbar) : "memory")

#define MBAR_EXPECT(mbar, bytes) \
    asm volatile("mbarrier.arrive.expect_tx.shared.b64 _, [%0], %1;" :: "r"(mbar), "r"(bytes) : "memory")

#define BULK_G2S(dst, src, bytes, mbar) \
    asm volatile("cp.async.bulk.shared::cluster.global.mbarrier::complete_tx::bytes [%0], [%1], %2, [%3];" \
                 :: "r"(dst), "l"(src), "r"(bytes), "r"(mbar) : "memory")

__device__ __forceinline__ void ldsm4(uint32_t& r0, uint32_t& r1, uint32_t& r2,
                                      uint32_t& r3, uint32_t addr) {
    asm volatile("ldmatrix.sync.aligned.m8n8.x4.shared.b16 {%0,%1,%2,%3}, [%4];"
                 : "=r"(r0), "=r"(r1), "=r"(r2), "=r"(r3) : "r"(addr));
}
__device__ __forceinline__ void mma16816(float& d0, float& d1, float& d2, float& d3,
                                         uint32_t a0, uint32_t a1, uint32_t a2, uint32_t a3,
                                         uint32_t b0, uint32_t b1) {
    asm volatile("mma.sync.aligned.m16n8k16.row.col.f32.f16.f16.f32 "
                 "{%0,%1,%2,%3}, {%4,%5,%6,%7}, {%8,%9}, {%0,%1,%2,%3};"
                 : "+f"(d0), "+f"(d1), "+f"(d2), "+f"(d3)
                 : "r"(a0), "r"(a1), "r"(a2), "r"(a3), "r"(b0), "r"(b1));
}

// ---------------------------------------------------------------------------
// Diffusion GEMM (R10/R12 version, verbatim).
// ---------------------------------------------------------------------------
__global__ __launch_bounds__(256, 2)
void gemm_tc(const __half* __restrict__ A2,
             const __half* __restrict__ B2,
             float* __restrict__ part)
{
    extern __shared__ __align__(16) char smem[];
    const uint32_t sb  = smem_u32(smem);
    const uint32_t st0 = sb + 64;

    const int tid  = threadIdx.x;
    const int wid  = tid >> 5, lane = tid & 31;
    const int wm   = wid >> 1;            // 0..3 -> m offset wm*32
    const int wn   = wid & 1;             // 0..1 -> n offset wn*64
    const int nb   = blockIdx.x;
    const int n0   = nb * NT;
    const int split = blockIdx.y;

    if (tid == 0) {
        MBAR_INIT(sb + 0, 1);  MBAR_INIT(sb + 8, 1);
        MBAR_INIT(sb + 16, 8); MBAR_INIT(sb + 24, 8);
    }
    __syncthreads();

    const __half* Asrc = A2 + (size_t)(split * NKT) * ATILE_H;
    const __half* Bsrc = B2 + (size_t)(nb * NKTOT + split * NKT) * BTILE_H;

    auto issue_load = [&](int tt) {       // thread 0 only
        const uint32_t s    = (uint32_t)(tt & 1);
        const uint32_t mbar = sb + s * 8;
        const uint32_t dst  = st0 + s * STAGESZ;
        MBAR_EXPECT(mbar, 49152u);
        BULK_G2S(dst,          Asrc + (size_t)tt * ATILE_H, 32768u, mbar);
        BULK_G2S(dst + 32768u, Bsrc + (size_t)tt * BTILE_H, 16384u, mbar);
    };

    if (tid == 0) { issue_load(0); issue_load(1); }

    const int r8  = lane & 7;
    const int seg = lane >> 3;            // 0..3
    const int sak = seg >> 1;
    const int sam = seg & 1;
    const int sbn = seg >> 1;
    const int sbk = seg & 1;
    uint32_t baseA[2];
#pragma unroll
    for (int mt = 0; mt < 2; mt++)
        baseA[mt] = (uint32_t)((wm * 32 + mt * 16 + sam * 8 + r8) * 256);
    uint32_t baseB[4];
#pragma unroll
    for (int p = 0; p < 4; p++)
        baseB[p] = (uint32_t)(32768 + (wn * 64 + p * 16 + sbn * 8 + r8) * 128);

    float acc[2][8][4] = {};

#pragma unroll 1
    for (int tt = 0; tt < NKT; tt++) {
        const uint32_t s   = (uint32_t)(tt & 1);
        const uint32_t par = (uint32_t)((tt >> 1) & 1);
        MBAR_WAIT(sb + s * 8, par);       // full[s]

        const uint32_t st = st0 + s * STAGESZ;

#pragma unroll
        for (int ks = 0; ks < 4; ks++) {
            const uint32_t offA = (uint32_t)(((ks * 2 + sak) ^ r8) << 4);
            const uint32_t offB = (uint32_t)(((ks * 2 + sbk) ^ r8) << 4);
            uint32_t ah[2][4], al[2][4];
#pragma unroll
            for (int mt = 0; mt < 2; mt++) {
                const uint32_t a = st + baseA[mt] + offA;
                ldsm4(ah[mt][0], ah[mt][1], ah[mt][2], ah[mt][3], a);
                ldsm4(al[mt][0], al[mt][1], al[mt][2], al[mt][3], a + 128);
            }
            uint32_t bh[8][2];
#pragma unroll
            for (int p = 0; p < 4; p++) {
                const uint32_t b = st + baseB[p] + offB;
                ldsm4(bh[2*p][0], bh[2*p][1], bh[2*p+1][0], bh[2*p+1][1], b);
            }
#pragma unroll
            for (int mt = 0; mt < 2; mt++)
#pragma unroll
                for (int nt = 0; nt < 8; nt++)
                    mma16816(acc[mt][nt][0], acc[mt][nt][1], acc[mt][nt][2], acc[mt][nt][3],
                             ah[mt][0], ah[mt][1], ah[mt][2], ah[mt][3],
                             bh[nt][0], bh[nt][1]);
#pragma unroll
            for (int mt = 0; mt < 2; mt++)
#pragma unroll
                for (int nt = 0; nt < 8; nt++)
                    mma16816(acc[mt][nt][0], acc[mt][nt][1], acc[mt][nt][2], acc[mt][nt][3],
                             al[mt][0], al[mt][1], al[mt][2], al[mt][3],
                             bh[nt][0], bh[nt][1]);
        }

        if (lane == 0) MBAR_ARRIVE(sb + 16 + s * 8);      // release stage s

        if (tid == 0 && tt + 2 < NKT) {
            MBAR_WAIT(sb + 16 + s * 8, par);              // empty[s]
            issue_load(tt + 2);
        }
    }

    const int mrow = lane >> 2;
    const int ncol = (lane & 3) * 2;
#pragma unroll
    for (int mt = 0; mt < 2; mt++) {
#pragma unroll
        for (int nt = 0; nt < 8; nt++) {
            const int c = wm * 32 + mt * 16 + mrow;
            const int n = n0 + wn * 64 + nt * 8 + ncol;
            float* d0 = part + ((size_t)(split * CC + c)) * NNODES + n;
            float* d1 = part + ((size_t)(split * CC + c + 8)) * NNODES + n;
            *reinterpret_cast<float2*>(d0) = make_float2(acc[mt][nt][0], acc[mt][nt][1]);
            *reinterpret_cast<float2*>(d1) = make_float2(acc[mt][nt][2], acc[mt][nt][3]);
        }
    }
}

// ---------------------------------------------------------------------------
// fp16 split helpers (8-wide)
// ---------------------------------------------------------------------------
__device__ __forceinline__ uint32_t pack2h(float a, float b) {
    __half2 h = __floats2half2_rn(a, b);
    return *reinterpret_cast<uint32_t*>(&h);
}
__device__ __forceinline__ void split8h(const float4 a, const float4 b,
                                        uint4& H, uint4& L) {
    __half h[8];
    h[0]=__float2half_rn(a.x); h[1]=__float2half_rn(a.y);
    h[2]=__float2half_rn(a.z); h[3]=__float2half_rn(a.w);
    h[4]=__float2half_rn(b.x); h[5]=__float2half_rn(b.y);
    h[6]=__float2half_rn(b.z); h[7]=__float2half_rn(b.w);
    H.x = ((uint32_t)__half_as_ushort(h[1]) << 16) | __half_as_ushort(h[0]);
    H.y = ((uint32_t)__half_as_ushort(h[3]) << 16) | __half_as_ushort(h[2]);
    H.z = ((uint32_t)__half_as_ushort(h[5]) << 16) | __half_as_ushort(h[4]);
    H.w = ((uint32_t)__half_as_ushort(h[7]) << 16) | __half_as_ushort(h[6]);
    L.x = pack2h(a.x - __half2float(h[0]), a.y - __half2float(h[1]));
    L.y = pack2h(a.z - __half2float(h[2]), a.w - __half2float(h[3]));
    L.z = pack2h(b.x - __half2float(h[4]), b.y - __half2float(h[5]));
    L.w = pack2h(b.z - __half2float(h[6]), b.w - __half2float(h[7]));
}

// S: fp32 [4096][4096] -> fp16 hi-only, tiled+swizzled B layout.
// 8 consecutive k per thread -> ONE 16B store.
__global__ __launch_bounds__(256)
void cvtS(const float4* __restrict__ in, __half* __restrict__ out, int n8)
{
    int i = blockIdx.x * 256 + threadIdx.x;
    if (i >= n8) return;
    float4 a = in[i * 2], b = in[i * 2 + 1];
    uint4 H;
    H.x = ((uint32_t)__half_as_ushort(__float2half_rn(a.y)) << 16) | __half_as_ushort(__float2half_rn(a.x));
    H.y = ((uint32_t)__half_as_ushort(__float2half_rn(a.w)) << 16) | __half_as_ushort(__float2half_rn(a.z));
    H.z = ((uint32_t)__half_as_ushort(__float2half_rn(b.y)) << 16) | __half_as_ushort(__float2half_rn(b.x));
    H.w = ((uint32_t)__half_as_ushort(__float2half_rn(b.w)) << 16) | __half_as_ushort(__float2half_rn(b.z));
    const int e  = i * 8;
    const int n  = e >> 12, k = e & 4095;
    const int nb = n >> 7,  r = n & 127;
    const int kt = k >> 6,  c = (k & 63) >> 3;
    const size_t base = (size_t)(nb * NKTOT + kt) * BTILE_H
                      + r * 64 + ((c ^ (r & 7)) << 3);
    *reinterpret_cast<uint4*>(out + base) = H;
}

// A-type index (element granularity, used by scalar writers)
__device__ __forceinline__ size_t a2_index(int row, int k) {
    const int kt = k >> 6, c = (k & 63) >> 3;
    return (size_t)kt * ATILE_H + row * 128 + ((c ^ (row & 7)) << 3) + (k & 7);
}

// A-type: fp32 [128][4096] -> fp16 hi/lo tiled; 8 k per thread, 2x 16B stores
__global__ __launch_bounds__(256)
void cvtA(const float4* __restrict__ in, __half* __restrict__ out, int n8)
{
    int i = blockIdx.x * 256 + threadIdx.x;
    if (i >= n8) return;
    uint4 H, L;
    split8h(in[i * 2], in[i * 2 + 1], H, L);
    const int e   = i * 8;
    const int row = e >> 12, k = e & 4095;
    const int kt = k >> 6, c = (k & 63) >> 3;
    const size_t base = (size_t)kt * ATILE_H + row * 128 + ((c ^ (row & 7)) << 3);
    *reinterpret_cast<uint4*>(out + base)      = H;
    *reinterpret_cast<uint4*>(out + base + 64) = L;
}

// ---------------------------------------------------------------------------
// split-K reduce + epilogue. MODE 0: Y = sum; 1: Y = sum + V; 2: relu(sum+V+b)
// ---------------------------------------------------------------------------
template <int MODE>
__global__ __launch_bounds__(256)
void reduce_splitk(const float* __restrict__ part, const float* __restrict__ V,
                   const float* __restrict__ bias, float* __restrict__ Yf,
                   __half* __restrict__ Y2)
{
    const int i = blockIdx.x * 256 + threadIdx.x;          // float8 index
    const float4* p = reinterpret_cast<const float4*>(part);
    const int STR = CC * NNODES / 4;
    float4 a = p[i * 2], b = p[i * 2 + 1];
#pragma unroll
    for (int s = 1; s < SPLITK; s++) {
        float4 qa = p[i * 2 + s * STR];
        float4 qb = p[i * 2 + 1 + s * STR];
        a.x += qa.x; a.y += qa.y; a.z += qa.z; a.w += qa.w;
        b.x += qb.x; b.y += qb.y; b.z += qb.z; b.w += qb.w;
    }
    if (MODE >= 1) {
        float4 va = reinterpret_cast<const float4*>(V)[i * 2];
        float4 vb = reinterpret_cast<const float4*>(V)[i * 2 + 1];
        a.x += va.x; a.y += va.y; a.z += va.z; a.w += va.w;
        b.x += vb.x; b.y += vb.y; b.z += vb.z; b.w += vb.w;
    }
    const int e  = i * 8;
    const int ch = e >> 12;                                // 0..127
    if (MODE == 2) {
        const float bv = bias[ch & 15];
        a.x = fmaxf(a.x + bv, 0.f); a.y = fmaxf(a.y + bv, 0.f);
        a.z = fmaxf(a.z + bv, 0.f); a.w = fmaxf(a.w + bv, 0.f);
        b.x = fmaxf(b.x + bv, 0.f); b.y = fmaxf(b.y + bv, 0.f);
        b.z = fmaxf(b.z + bv, 0.f); b.w = fmaxf(b.w + bv, 0.f);
    }
    if (Yf) {
        reinterpret_cast<float4*>(Yf)[i * 2]     = a;
        reinterpret_cast<float4*>(Yf)[i * 2 + 1] = b;
    }
    if (Y2) {
        uint4 H, L;
        split8h(a, b, H, L);
        const int k = e & 4095;
        const int kt = k >> 6, c = (k & 63) >> 3;
        const size_t base = (size_t)kt * ATILE_H + ch * 128 + ((c ^ (ch & 7)) << 3);
        *reinterpret_cast<uint4*>(Y2 + base)      = H;
        *reinterpret_cast<uint4*>(Y2 + base + 64) = L;
    }
}

// ---------------------------------------------------------------------------
// Fused 16->32 layer head (unchanged from R12)
// ---------------------------------------------------------------------------
__global__ __launch_bounds__(256)
void layer_fused(const float* __restrict__ part, const float* __restrict__ z1f,
                 const float* __restrict__ z0, const float* __restrict__ Wa,
                 const float* __restrict__ ba, const float* __restrict__ Wb,
                 float* __restrict__ v0, float* __restrict__ v1,
                 __half* __restrict__ v2c)
{
    __shared__ float Ws [32 * 48];
    __shared__ float Ws2[16 * 96];
    __shared__ float bs [32];
    const int tid = threadIdx.x;
    for (int i = tid; i < 32 * 48; i += 256) Ws[i]  = Wa[i];
    for (int i = tid; i < 16 * 96; i += 256) Ws2[i] = Wb[i];
    if (tid < 32) bs[tid] = ba[tid];
    __syncthreads();

    const int n = blockIdx.x * 256 + tid;
    const int b = blockIdx.y;

    float y[32];
#pragma unroll
    for (int g = 0; g < 32; g++) y[g] = bs[g];

#pragma unroll
    for (int f = 0; f < 16; f++) {
        float zv = z0[((size_t)(b * 16 + f)) * NNODES + n];
#pragma unroll
        for (int g = 0; g < 32; g++) y[g] += Ws[g * 48 + f] * zv;
    }
#pragma unroll
    for (int f = 0; f < 16; f++) {
        float zv = z1f[((size_t)(b * 16 + f)) * NNODES + n];
#pragma unroll
        for (int g = 0; g < 32; g++) y[g] += Ws[g * 48 + 16 + f] * zv;
    }
#pragma unroll
    for (int f = 0; f < 16; f++) {
        float zv = 0.f;
#pragma unroll
        for (int s = 0; s < SPLITK; s++)
            zv += part[((size_t)(s * CC + b * 16 + f)) * NNODES + n];
#pragma unroll
        for (int g = 0; g < 32; g++) y[g] += Ws[g * 48 + 32 + f] * zv;
    }
#pragma unroll
    for (int g = 0; g < 32; g++) y[g] = fmaxf(y[g], 0.f);

#pragma unroll
    for (int g = 0; g < 16; g++) {
        float a0 = 0.f, a1 = 0.f, a2 = 0.f;
#pragma unroll
        for (int f = 0; f < 32; f++) {
            const float yv = y[f];
            a0 += Ws2[g * 96 +       f] * yv;
            a1 += Ws2[g * 96 + 32 +  f] * yv;
            a2 += Ws2[g * 96 + 64 +  f] * yv;
        }
        v0[((size_t)(b * 16 + g)) * NNODES + n] = a0;
        v1[((size_t)(b * 16 + g)) * NNODES + n] = a1;
        const size_t o = a2_index(b * 16 + g, n);
        __half h = __float2half_rn(a2);
        v2c[o]      = h;
        v2c[o + 64] = __float2half_rn(a2 - __half2float(h));
    }
}

// ---------------------------------------------------------------------------
// MLP head (unchanged)
// ---------------------------------------------------------------------------
__global__ __launch_bounds__(256)
void mlp1b(const float* __restrict__ y, const float* __restrict__ W1,
           float* __restrict__ hp)
{
    const int jg = blockIdx.x;
    const int ks = blockIdx.y;
    const float4* Y4 = reinterpret_cast<const float4*>(y);
    const float4* W4 = reinterpret_cast<const float4*>(W1);

    float s[8][8] = {};
    for (int i = threadIdx.x; i < 2048; i += 256) {
        const int off = ks * 2048 + i;
        float4 yv[8];
#pragma unroll
        for (int b = 0; b < 8; b++) yv[b] = Y4[(size_t)b * 16384 + off];
#pragma unroll
        for (int jj = 0; jj < 8; jj++) {
            float4 w = W4[(size_t)(jg * 8 + jj) * 16384 + off];
#pragma unroll
            for (int b = 0; b < 8; b++)
                s[jj][b] += yv[b].x * w.x + yv[b].y * w.y + yv[b].z * w.z + yv[b].w * w.w;
        }
    }
    __shared__ float red[8][64];
    const int wid = threadIdx.x >> 5, lane = threadIdx.x & 31;
#pragma unroll
    for (int jj = 0; jj < 8; jj++)
#pragma unroll
        for (int b = 0; b < 8; b++) {
            float v = s[jj][b];
#pragma unroll
            for (int o = 16; o > 0; o >>= 1) v += __shfl_down_sync(0xffffffffu, v, o);
            if (lane == 0) red[wid][jj * 8 + b] = v;
        }
    __syncthreads();
    if (threadIdx.x < 64) {
        const int jj = threadIdx.x >> 3, b = threadIdx.x & 7;
        float t = 0.f;
#pragma unroll
        for (int w = 0; w < 8; w++) t += red[w][jj * 8 + b];
        hp[((size_t)ks * 8 + b) * 64 + jg * 8 + jj] = t;
    }
}

__global__ __launch_bounds__(64)
void mlp2b(const float* __restrict__ hp, const float* __restrict__ b1,
           const float* __restrict__ W2, const float* __restrict__ b2,
           float* __restrict__ out)
{
    const int b = blockIdx.x, j = threadIdx.x;
    float hv = b1[j];
#pragma unroll
    for (int s = 0; s < 8; s++) hv += hp[((size_t)s * 8 + b) * 64 + j];
    float v = fmaxf(hv, 0.f) * W2[j];
#pragma unroll
    for (int o = 16; o > 0; o >>= 1) v += __shfl_down_sync(0xffffffffu, v, o);
    __shared__ float s2[2];
    if ((j & 31) == 0) s2[j >> 5] = v;
    __syncthreads();
    if (j == 0) out[b] = s2[0] + s2[1] + b2[0];
}

// ---------------------------------------------------------------------------
extern "C" void kernel_launch(void* const* d_in, const int* in_sizes, int n_in,
                              void* d_out, int out_size)
{
    const float* x   = (const float*)d_in[0];
    const float* Sc  = (const float*)d_in[1];
    const float* Sl  = (const float*)d_in[2];
    const float* Wc1 = (const float*)d_in[3];
    const float* bc1 = (const float*)d_in[4];
    const float* Wc2 = (const float*)d_in[5];
    const float* bc2 = (const float*)d_in[6];
    const float* Wl1 = (const float*)d_in[7];
    const float* bl1 = (const float*)d_in[8];
    const float* Wl2 = (const float*)d_in[9];
    const float* bl2 = (const float*)d_in[10];
    const float* Wm1 = (const float*)d_in[11];
    const float* bm1 = (const float*)d_in[12];
    const float* Wm2 = (const float*)d_in[13];
    const float* bm2 = (const float*)d_in[14];
    float* out = (float*)d_out;

    cudaFuncSetAttribute(gemm_tc, cudaFuncAttributeMaxDynamicSharedMemorySize, SMEMSZ);

    // side stream + events (created once, outside graph capture: the harness
    // runs kernel_launch uncaptured for correctness before capturing)
    static cudaStream_t s2 = nullptr;
    static cudaEvent_t evFork = nullptr, evJoin = nullptr;
    if (s2 == nullptr) {
        cudaStreamCreateWithFlags(&s2, cudaStreamNonBlocking);
        cudaEventCreateWithFlags(&evFork, cudaEventDisableTiming);
        cudaEventCreateWithFlags(&evJoin, cudaEventDisableTiming);
    }

    __half *Sc2, *Sl2, *x2, *a2, *b2;
    float *part, *z1f, *v0, *v1, *y16, *hp;
    cudaGetSymbolAddress((void**)&Sc2, g_Sc2); cudaGetSymbolAddress((void**)&Sl2, g_Sl2);
    cudaGetSymbolAddress((void**)&x2, g_x2);
    cudaGetSymbolAddress((void**)&a2, g_a2);   cudaGetSymbolAddress((void**)&b2, g_b2);
    cudaGetSymbolAddress((void**)&part, g_part);
    cudaGetSymbolAddress((void**)&z1f, g_z1f);
    cudaGetSymbolAddress((void**)&v0, g_v0);   cudaGetSymbolAddress((void**)&v1, g_v1);
    cudaGetSymbolAddress((void**)&y16, g_y16);
    cudaGetSymbolAddress((void**)&hp, g_hp);

    const int SN8 = NNODES * NNODES / 8;          // 2M 8-elem groups
    const int XN8 = CC * NNODES / 8;              // 64K 8-elem groups

    // fork: convert Sl2 on the side stream (needed only from layer 3)
    cudaEventRecord(evFork, 0);
    cudaStreamWaitEvent(s2, evFork, 0);
    cvtS<<<SN8 / 256, 256, 0, s2>>>((const float4*)Sl, Sl2, SN8);
    cudaEventRecord(evJoin, s2);

    cvtS<<<SN8 / 256, 256>>>((const float4*)Sc, Sc2, SN8);
    cvtA<<<XN8 / 256, 256>>>((const float4*)x,  x2,  XN8);

    const dim3 gG(NNODES / NT, SPLITK);           // 32 x 8 = 256 CTAs
    const dim3 gR(CC * NNODES / 8 / 256);         // 256 blocks (8 elems/thr)
    const dim3 gF(NNODES / 256, BATCH);           // 16 x 8 fused head

    // ---- Layer 1 (clique, 16 -> 32) + Layer-2 projections, fused ----
    gemm_tc<<<gG, 256, SMEMSZ>>>(x2, Sc2, part);
    reduce_splitk<0><<<gR, 256>>>(part, nullptr, nullptr, z1f, a2);
    gemm_tc<<<gG, 256, SMEMSZ>>>(a2, Sc2, part);
    layer_fused<<<gF, 256>>>(part, z1f, x, Wc1, bc1, Wc2, v0, v1, b2);

    // ---- Layer 2 (clique, 32 -> 16): Horner ----
    gemm_tc<<<gG, 256, SMEMSZ>>>(b2, Sc2, part);
    reduce_splitk<1><<<gR, 256>>>(part, v1, nullptr, nullptr, a2);
    gemm_tc<<<gG, 256, SMEMSZ>>>(a2, Sc2, part);
    reduce_splitk<2><<<gR, 256>>>(part, v0, bc2, y16, b2);

    // join: Sl2 must be ready before the line layers
    cudaStreamWaitEvent(0, evJoin, 0);

    // ---- Layer 3 (line, 16 -> 32) + Layer-4 projections, fused ----
    gemm_tc<<<gG, 256, SMEMSZ>>>(b2, Sl2, part);
    reduce_splitk<0><<<gR, 256>>>(part, nullptr, nullptr, z1f, a2);
    gemm_tc<<<gG, 256, SMEMSZ>>>(a2, Sl2, part);
    layer_fused<<<gF, 256>>>(part, z1f, y16, Wl1, bl1, Wl2, v0, v1, b2);

    // ---- Layer 4 (line, 32 -> 16): Horner ----
    gemm_tc<<<gG, 256, SMEMSZ>>>(b2, Sl2, part);
    reduce_splitk<1><<<gR, 256>>>(part, v1, nullptr, nullptr, a2);
    gemm_tc<<<gG, 256, SMEMSZ>>>(a2, Sl2, part);
    reduce_splitk<2><<<gR, 256>>>(part, v0, bl2, y16, nullptr);

    // ---- MLP head ----
    mlp1b<<<dim3(8, 8), 256>>>(y16, Wm1, hp);
    mlp2b<<<BATCH, 64>>>(hp, bm1, Wm2, bm2, out);
}

// round 14
// speedup vs baseline: 1.1598x; 1.0021x over previous
#include <cuda_runtime.h>
#include <cuda_fp16.h>
#include <cstdint>

// ---------------------------------------------------------------------------
// SelectionGNN (clique+line), B=8, N=4096, E=1, K=3, F=[16,32,16]
// Diffusion GEMMs (8x: 128x4096x4096) via mma.sync fp16 2-pass
// (D = Ah*Bh + Al*Bh, fp32 accum; pinned at sm_103a mma.sync HMMA floor).
// R14: SPLITK=4, NT=64 (grid 64x4 = 256 CTAs, 2/SM) -> part halves to 8.4MB,
// reduce kernels halve. Operands pre-tiled+pre-swizzled, TMA bulk loads,
// full/empty mbarrier pipeline. 16->32 layers fused. Sl conversion forked.
// ---------------------------------------------------------------------------

#define NNODES 4096
#define BATCH  8
#define CC     128                 // channels = B*16 (GEMM M)
#define NT     64                  // n-tile per CTA
#define SPLITK 4
#define KC     (NNODES / SPLITK)   // 1024 k per CTA
#define NKT    (KC / 64)           // 16 k-tiles (64 k each)
#define NKTOT  (NNODES / 64)       // 64 k-tiles total

#define ATILE_H  16384             // A tile halves (32KB): 128 rows x 256B
#define BTILE_H  4096              // B tile halves (8KB): 64 rows x 128B
#define STAGESZ  40960             // bytes: A(32K) + B(8K)
#define NSTAGE   2
#define SMEMSZ   (64 + NSTAGE * STAGESZ)   // 81984 -> 2 CTAs/SM fit

// ---------------- scratch (device globals; allocation is forbidden) --------
__device__ __align__(256) __half g_Sc2[(size_t)NNODES * NNODES];   // 32MB tiled
__device__ __align__(256) __half g_Sl2[(size_t)NNODES * NNODES];   // 32MB tiled
__device__ __align__(256) __half g_x2 [NKTOT * ATILE_H];           // 2MB tiled
__device__ __align__(256) __half g_a2 [NKTOT * ATILE_H];
__device__ __align__(256) __half g_b2 [NKTOT * ATILE_H];
__device__ __align__(256) float g_part[SPLITK * CC * NNODES];      // 8.4 MB
__device__ __align__(256) float g_z1f [CC * NNODES];
__device__ __align__(256) float g_v0  [CC * NNODES];
__device__ __align__(256) float g_v1  [CC * NNODES];
__device__ __align__(256) float g_y16 [CC * NNODES];
__device__ __align__(256) float g_hp  [8 * BATCH * 64];

// ---------------- PTX helpers (baseline sm_90-level PTX only) ---------------
__device__ __forceinline__ uint32_t smem_u32(const void* p) {
    uint32_t a;
    asm("{ .reg .u64 t; cvta.to.shared.u64 t, %1; cvt.u32.u64 %0, t; }" : "=r"(a) : "l"(p));
    return a;
}
#define MBAR_INIT(a, c) asm volatile("mbarrier.init.shared.b64 [%0], %1;" :: "r"(a), "r"(c) : "memory")

#define MBAR_WAIT(mbar, par) do {                                              \
    uint32_t _m = (mbar), _p = (par), _d;                                      \
    asm volatile("{ .reg .pred p;"                                             \
        " mbarrier.try_wait.parity.acquire.cta.shared::cta.b64 p, [%1], %2;"   \
        " selp.b32 %0, 1, 0, p; }" : "=r"(_d) : "r"(_m), "r"(_p) : "memory");  \
    if (!_d) {                                                                 \
        asm volatile("{ .reg .pred P1;"                                        \
        " W%=: mbarrier.try_wait.parity.acquire.cta.shared::cta.b64 P1, [%0], %1, 0x989680;" \
        " @P1 bra.uni D%=; bra.uni W%=; D%=: }" :: "r"(_m), "r"(_p) : "memory"); } \
} while (0)

#define MBAR_ARRIVE(mbar) \
    asm volatile("mbarrier.arrive.shared.b64 _, [%0];" :: "r"(mbar) : "memory")

#define MBAR_EXPECT(mbar, bytes) \
    asm volatile("mbarrier.arrive.expect_tx.shared.b64 _, [%0], %1;" :: "r"(mbar), "r"(bytes) : "memory")

#define BULK_G2S(dst, src, bytes, mbar) \
    asm volatile("cp.async.bulk.shared::cluster.global.mbarrier::complete_tx::bytes [%0], [%1], %2, [%3];" \
                 :: "r"(dst), "l"(src), "r"(bytes), "r"(mbar) : "memory")

__device__ __forceinline__ void ldsm4(uint32_t& r0, uint32_t& r1, uint32_t& r2,
                                      uint32_t& r3, uint32_t addr) {
    asm volatile("ldmatrix.sync.aligned.m8n8.x4.shared.b16 {%0,%1,%2,%3}, [%4];"
                 : "=r"(r0), "=r"(r1), "=r"(r2), "=r"(r3) : "r"(addr));
}
__device__ __forceinline__ void mma16816(float& d0, float& d1, float& d2, float& d3,
                                         uint32_t a0, uint32_t a1, uint32_t a2, uint32_t a3,
                                         uint32_t b0, uint32_t b1) {
    asm volatile("mma.sync.aligned.m16n8k16.row.col.f32.f16.f16.f32 "
                 "{%0,%1,%2,%3}, {%4,%5,%6,%7}, {%8,%9}, {%0,%1,%2,%3};"
                 : "+f"(d0), "+f"(d1), "+f"(d2), "+f"(d3)
                 : "r"(a0), "r"(a1), "r"(a2), "r"(a3), "r"(b0), "r"(b1));
}

// ---------------------------------------------------------------------------
// Diffusion GEMM. A2 tiled [64 kt][128r][256B], B2 tiled [64 nb][64 kt][64r][128B]
// grid = (64 nb, 4 split), 256 threads, 8 warps (4m x 2n), warp tile 32x32.
// ---------------------------------------------------------------------------
__global__ __launch_bounds__(256, 2)
void gemm_tc(const __half* __restrict__ A2,
             const __half* __restrict__ B2,
             float* __restrict__ part)
{
    extern __shared__ __align__(16) char smem[];
    const uint32_t sb  = smem_u32(smem);
    const uint32_t st0 = sb + 64;

    const int tid  = threadIdx.x;
    const int wid  = tid >> 5, lane = tid & 31;
    const int wm   = wid >> 1;            // 0..3 -> m offset wm*32
    const int wn   = wid & 1;             // 0..1 -> n offset wn*32
    const int nb   = blockIdx.x;
    const int n0   = nb * NT;
    const int split = blockIdx.y;

    if (tid == 0) {
        MBAR_INIT(sb + 0, 1);  MBAR_INIT(sb + 8, 1);
        MBAR_INIT(sb + 16, 8); MBAR_INIT(sb + 24, 8);
    }
    __syncthreads();

    const __half* Asrc = A2 + (size_t)(split * NKT) * ATILE_H;
    const __half* Bsrc = B2 + (size_t)(nb * NKTOT + split * NKT) * BTILE_H;

    auto issue_load = [&](int tt) {       // thread 0 only
        const uint32_t s    = (uint32_t)(tt & 1);
        const uint32_t mbar = sb + s * 8;
        const uint32_t dst  = st0 + s * STAGESZ;
        MBAR_EXPECT(mbar, 40960u);
        BULK_G2S(dst,          Asrc + (size_t)tt * ATILE_H, 32768u, mbar);
        BULK_G2S(dst + 32768u, Bsrc + (size_t)tt * BTILE_H, 8192u,  mbar);
    };

    if (tid == 0) { issue_load(0); issue_load(1); }

    const int r8  = lane & 7;
    const int seg = lane >> 3;            // 0..3
    const int sak = seg >> 1;
    const int sam = seg & 1;
    const int sbn = seg >> 1;
    const int sbk = seg & 1;
    uint32_t baseA[2];
#pragma unroll
    for (int mt = 0; mt < 2; mt++)
        baseA[mt] = (uint32_t)((wm * 32 + mt * 16 + sam * 8 + r8) * 256);
    uint32_t baseB[2];
#pragma unroll
    for (int p = 0; p < 2; p++)
        baseB[p] = (uint32_t)(32768 + (wn * 32 + p * 16 + sbn * 8 + r8) * 128);

    float acc[2][4][4] = {};

#pragma unroll 1
    for (int tt = 0; tt < NKT; tt++) {
        const uint32_t s   = (uint32_t)(tt & 1);
        const uint32_t par = (uint32_t)((tt >> 1) & 1);
        MBAR_WAIT(sb + s * 8, par);       // full[s]

        const uint32_t st = st0 + s * STAGESZ;

#pragma unroll
        for (int ks = 0; ks < 4; ks++) {
            const uint32_t offA = (uint32_t)(((ks * 2 + sak) ^ r8) << 4);
            const uint32_t offB = (uint32_t)(((ks * 2 + sbk) ^ r8) << 4);
            uint32_t ah[2][4], al[2][4];
#pragma unroll
            for (int mt = 0; mt < 2; mt++) {
                const uint32_t a = st + baseA[mt] + offA;
                ldsm4(ah[mt][0], ah[mt][1], ah[mt][2], ah[mt][3], a);
                ldsm4(al[mt][0], al[mt][1], al[mt][2], al[mt][3], a + 128);
            }
            uint32_t bh[4][2];
#pragma unroll
            for (int p = 0; p < 2; p++) {
                const uint32_t b = st + baseB[p] + offB;
                ldsm4(bh[2*p][0], bh[2*p][1], bh[2*p+1][0], bh[2*p+1][1], b);
            }
#pragma unroll
            for (int mt = 0; mt < 2; mt++)
#pragma unroll
                for (int nt = 0; nt < 4; nt++)
                    mma16816(acc[mt][nt][0], acc[mt][nt][1], acc[mt][nt][2], acc[mt][nt][3],
                             ah[mt][0], ah[mt][1], ah[mt][2], ah[mt][3],
                             bh[nt][0], bh[nt][1]);
#pragma unroll
            for (int mt = 0; mt < 2; mt++)
#pragma unroll
                for (int nt = 0; nt < 4; nt++)
                    mma16816(acc[mt][nt][0], acc[mt][nt][1], acc[mt][nt][2], acc[mt][nt][3],
                             al[mt][0], al[mt][1], al[mt][2], al[mt][3],
                             bh[nt][0], bh[nt][1]);
        }

        if (lane == 0) MBAR_ARRIVE(sb + 16 + s * 8);      // release stage s

        if (tid == 0 && tt + 2 < NKT) {
            MBAR_WAIT(sb + 16 + s * 8, par);              // empty[s]
            issue_load(tt + 2);
        }
    }

    const int mrow = lane >> 2;
    const int ncol = (lane & 3) * 2;
#pragma unroll
    for (int mt = 0; mt < 2; mt++) {
#pragma unroll
        for (int nt = 0; nt < 4; nt++) {
            const int c = wm * 32 + mt * 16 + mrow;
            const int n = n0 + wn * 32 + nt * 8 + ncol;
            float* d0 = part + ((size_t)(split * CC + c)) * NNODES + n;
            float* d1 = part + ((size_t)(split * CC + c + 8)) * NNODES + n;
            *reinterpret_cast<float2*>(d0) = make_float2(acc[mt][nt][0], acc[mt][nt][1]);
            *reinterpret_cast<float2*>(d1) = make_float2(acc[mt][nt][2], acc[mt][nt][3]);
        }
    }
}

// ---------------------------------------------------------------------------
// fp16 split helpers (8-wide)
// ---------------------------------------------------------------------------
__device__ __forceinline__ uint32_t pack2h(float a, float b) {
    __half2 h = __floats2half2_rn(a, b);
    return *reinterpret_cast<uint32_t*>(&h);
}
__device__ __forceinline__ void split8h(const float4 a, const float4 b,
                                        uint4& H, uint4& L) {
    __half h[8];
    h[0]=__float2half_rn(a.x); h[1]=__float2half_rn(a.y);
    h[2]=__float2half_rn(a.z); h[3]=__float2half_rn(a.w);
    h[4]=__float2half_rn(b.x); h[5]=__float2half_rn(b.y);
    h[6]=__float2half_rn(b.z); h[7]=__float2half_rn(b.w);
    H.x = ((uint32_t)__half_as_ushort(h[1]) << 16) | __half_as_ushort(h[0]);
    H.y = ((uint32_t)__half_as_ushort(h[3]) << 16) | __half_as_ushort(h[2]);
    H.z = ((uint32_t)__half_as_ushort(h[5]) << 16) | __half_as_ushort(h[4]);
    H.w = ((uint32_t)__half_as_ushort(h[7]) << 16) | __half_as_ushort(h[6]);
    L.x = pack2h(a.x - __half2float(h[0]), a.y - __half2float(h[1]));
    L.y = pack2h(a.z - __half2float(h[2]), a.w - __half2float(h[3]));
    L.z = pack2h(b.x - __half2float(h[4]), b.y - __half2float(h[5]));
    L.w = pack2h(b.z - __half2float(h[6]), b.w - __half2float(h[7]));
}

// S: fp32 [4096][4096] -> fp16 hi-only, tiled+swizzled B layout (NT=64):
// tile (nb = n>>6, kt = k>>6), row r = n&63, chunk c = (k&63)>>3
__global__ __launch_bounds__(256)
void cvtS(const float4* __restrict__ in, __half* __restrict__ out, int n8)
{
    int i = blockIdx.x * 256 + threadIdx.x;
    if (i >= n8) return;
    float4 a = in[i * 2], b = in[i * 2 + 1];
    uint4 H;
    H.x = ((uint32_t)__half_as_ushort(__float2half_rn(a.y)) << 16) | __half_as_ushort(__float2half_rn(a.x));
    H.y = ((uint32_t)__half_as_ushort(__float2half_rn(a.w)) << 16) | __half_as_ushort(__float2half_rn(a.z));
    H.z = ((uint32_t)__half_as_ushort(__float2half_rn(b.y)) << 16) | __half_as_ushort(__float2half_rn(b.x));
    H.w = ((uint32_t)__half_as_ushort(__float2half_rn(b.w)) << 16) | __half_as_ushort(__float2half_rn(b.z));
    const int e  = i * 8;
    const int n  = e >> 12, k = e & 4095;
    const int nb = n >> 6,  r = n & 63;
    const int kt = k >> 6,  c = (k & 63) >> 3;
    const size_t base = (size_t)(nb * NKTOT + kt) * BTILE_H
                      + r * 64 + ((c ^ (r & 7)) << 3);
    *reinterpret_cast<uint4*>(out + base) = H;
}

// A-type index (element granularity)
__device__ __forceinline__ size_t a2_index(int row, int k) {
    const int kt = k >> 6, c = (k & 63) >> 3;
    return (size_t)kt * ATILE_H + row * 128 + ((c ^ (row & 7)) << 3) + (k & 7);
}

// A-type: fp32 [128][4096] -> fp16 hi/lo tiled; 8 k per thread
__global__ __launch_bounds__(256)
void cvtA(const float4* __restrict__ in, __half* __restrict__ out, int n8)
{
    int i = blockIdx.x * 256 + threadIdx.x;
    if (i >= n8) return;
    uint4 H, L;
    split8h(in[i * 2], in[i * 2 + 1], H, L);
    const int e   = i * 8;
    const int row = e >> 12, k = e & 4095;
    const int kt = k >> 6, c = (k & 63) >> 3;
    const size_t base = (size_t)kt * ATILE_H + row * 128 + ((c ^ (row & 7)) << 3);
    *reinterpret_cast<uint4*>(out + base)      = H;
    *reinterpret_cast<uint4*>(out + base + 64) = L;
}

// ---------------------------------------------------------------------------
// split-K reduce + epilogue. MODE 0: Y = sum; 1: Y = sum + V; 2: relu(sum+V+b)
// ---------------------------------------------------------------------------
template <int MODE>
__global__ __launch_bounds__(256)
void reduce_splitk(const float* __restrict__ part, const float* __restrict__ V,
                   const float* __restrict__ bias, float* __restrict__ Yf,
                   __half* __restrict__ Y2)
{
    const int i = blockIdx.x * 256 + threadIdx.x;          // float8 index
    const float4* p = reinterpret_cast<const float4*>(part);
    const int STR = CC * NNODES / 4;
    float4 a = p[i * 2], b = p[i * 2 + 1];
#pragma unroll
    for (int s = 1; s < SPLITK; s++) {
        float4 qa = p[i * 2 + s * STR];
        float4 qb = p[i * 2 + 1 + s * STR];
        a.x += qa.x; a.y += qa.y; a.z += qa.z; a.w += qa.w;
        b.x += qb.x; b.y += qb.y; b.z += qb.z; b.w += qb.w;
    }
    if (MODE >= 1) {
        float4 va = reinterpret_cast<const float4*>(V)[i * 2];
        float4 vb = reinterpret_cast<const float4*>(V)[i * 2 + 1];
        a.x += va.x; a.y += va.y; a.z += va.z; a.w += va.w;
        b.x += vb.x; b.y += vb.y; b.z += vb.z; b.w += vb.w;
    }
    const int e  = i * 8;
    const int ch = e >> 12;                                // 0..127
    if (MODE == 2) {
        const float bv = bias[ch & 15];
        a.x = fmaxf(a.x + bv, 0.f); a.y = fmaxf(a.y + bv, 0.f);
        a.z = fmaxf(a.z + bv, 0.f); a.w = fmaxf(a.w + bv, 0.f);
        b.x = fmaxf(b.x + bv, 0.f); b.y = fmaxf(b.y + bv, 0.f);
        b.z = fmaxf(b.z + bv, 0.f); b.w = fmaxf(b.w + bv, 0.f);
    }
    if (Yf) {
        reinterpret_cast<float4*>(Yf)[i * 2]     = a;
        reinterpret_cast<float4*>(Yf)[i * 2 + 1] = b;
    }
    if (Y2) {
        uint4 H, L;
        split8h(a, b, H, L);
        const int k = e & 4095;
        const int kt = k >> 6, c = (k & 63) >> 3;
        const size_t base = (size_t)kt * ATILE_H + ch * 128 + ((c ^ (ch & 7)) << 3);
        *reinterpret_cast<uint4*>(Y2 + base)      = H;
        *reinterpret_cast<uint4*>(Y2 + base + 64) = L;
    }
}

// ---------------------------------------------------------------------------
// Fused 16->32 layer head (SPLITK=4)
// ---------------------------------------------------------------------------
__global__ __launch_bounds__(256)
void layer_fused(const float* __restrict__ part, const float* __restrict__ z1f,
                 const float* __restrict__ z0, const float* __restrict__ Wa,
                 const float* __restrict__ ba, const float* __restrict__ Wb,
                 float* __restrict__ v0, float* __restrict__ v1,
                 __half* __restrict__ v2c)
{
    __shared__ float Ws [32 * 48];
    __shared__ float Ws2[16 * 96];
    __shared__ float bs [32];
    const int tid = threadIdx.x;
    for (int i = tid; i < 32 * 48; i += 256) Ws[i]  = Wa[i];
    for (int i = tid; i < 16 * 96; i += 256) Ws2[i] = Wb[i];
    if (tid < 32) bs[tid] = ba[tid];
    __syncthreads();

    const int n = blockIdx.x * 256 + tid;
    const int b = blockIdx.y;

    float y[32];
#pragma unroll
    for (int g = 0; g < 32; g++) y[g] = bs[g];

#pragma unroll
    for (int f = 0; f < 16; f++) {
        float zv = z0[((size_t)(b * 16 + f)) * NNODES + n];
#pragma unroll
        for (int g = 0; g < 32; g++) y[g] += Ws[g * 48 + f] * zv;
    }
#pragma unroll
    for (int f = 0; f < 16; f++) {
        float zv = z1f[((size_t)(b * 16 + f)) * NNODES + n];
#pragma unroll
        for (int g = 0; g < 32; g++) y[g] += Ws[g * 48 + 16 + f] * zv;
    }
#pragma unroll
    for (int f = 0; f < 16; f++) {
        float zv = 0.f;
#pragma unroll
        for (int s = 0; s < SPLITK; s++)
            zv += part[((size_t)(s * CC + b * 16 + f)) * NNODES + n];
#pragma unroll
        for (int g = 0; g < 32; g++) y[g] += Ws[g * 48 + 32 + f] * zv;
    }
#pragma unroll
    for (int g = 0; g < 32; g++) y[g] = fmaxf(y[g], 0.f);

#pragma unroll
    for (int g = 0; g < 16; g++) {
        float a0 = 0.f, a1 = 0.f, a2 = 0.f;
#pragma unroll
        for (int f = 0; f < 32; f++) {
            const float yv = y[f];
            a0 += Ws2[g * 96 +       f] * yv;
            a1 += Ws2[g * 96 + 32 +  f] * yv;
            a2 += Ws2[g * 96 + 64 +  f] * yv;
        }
        v0[((size_t)(b * 16 + g)) * NNODES + n] = a0;
        v1[((size_t)(b * 16 + g)) * NNODES + n] = a1;
        const size_t o = a2_index(b * 16 + g, n);
        __half h = __float2half_rn(a2);
        v2c[o]      = h;
        v2c[o + 64] = __float2half_rn(a2 - __half2float(h));
    }
}

// ---------------------------------------------------------------------------
// MLP head (unchanged)
// ---------------------------------------------------------------------------
__global__ __launch_bounds__(256)
void mlp1b(const float* __restrict__ y, const float* __restrict__ W1,
           float* __restrict__ hp)
{
    const int jg = blockIdx.x;
    const int ks = blockIdx.y;
    const float4* Y4 = reinterpret_cast<const float4*>(y);
    const float4* W4 = reinterpret_cast<const float4*>(W1);

    float s[8][8] = {};
    for (int i = threadIdx.x; i < 2048; i += 256) {
        const int off = ks * 2048 + i;
        float4 yv[8];
#pragma unroll
        for (int b = 0; b < 8; b++) yv[b] = Y4[(size_t)b * 16384 + off];
#pragma unroll
        for (int jj = 0; jj < 8; jj++) {
            float4 w = W4[(size_t)(jg * 8 + jj) * 16384 + off];
#pragma unroll
            for (int b = 0; b < 8; b++)
                s[jj][b] += yv[b].x * w.x + yv[b].y * w.y + yv[b].z * w.z + yv[b].w * w.w;
        }
    }
    __shared__ float red[8][64];
    const int wid = threadIdx.x >> 5, lane = threadIdx.x & 31;
#pragma unroll
    for (int jj = 0; jj < 8; jj++)
#pragma unroll
        for (int b = 0; b < 8; b++) {
            float v = s[jj][b];
#pragma unroll
            for (int o = 16; o > 0; o >>= 1) v += __shfl_down_sync(0xffffffffu, v, o);
            if (lane == 0) red[wid][jj * 8 + b] = v;
        }
    __syncthreads();
    if (threadIdx.x < 64) {
        const int jj = threadIdx.x >> 3, b = threadIdx.x & 7;
        float t = 0.f;
#pragma unroll
        for (int w = 0; w < 8; w++) t += red[w][jj * 8 + b];
        hp[((size_t)ks * 8 + b) * 64 + jg * 8 + jj] = t;
    }
}

__global__ __launch_bounds__(64)
void mlp2b(const float* __restrict__ hp, const float* __restrict__ b1,
           const float* __restrict__ W2, const float* __restrict__ b2,
           float* __restrict__ out)
{
    const int b = blockIdx.x, j = threadIdx.x;
    float hv = b1[j];
#pragma unroll
    for (int s = 0; s < 8; s++) hv += hp[((size_t)s * 8 + b) * 64 + j];
    float v = fmaxf(hv, 0.f) * W2[j];
#pragma unroll
    for (int o = 16; o > 0; o >>= 1) v += __shfl_down_sync(0xffffffffu, v, o);
    __shared__ float s2[2];
    if ((j & 31) == 0) s2[j >> 5] = v;
    __syncthreads();
    if (j == 0) out[b] = s2[0] + s2[1] + b2[0];
}

// ---------------------------------------------------------------------------
extern "C" void kernel_launch(void* const* d_in, const int* in_sizes, int n_in,
                              void* d_out, int out_size)
{
    const float* x   = (const float*)d_in[0];
    const float* Sc  = (const float*)d_in[1];
    const float* Sl  = (const float*)d_in[2];
    const float* Wc1 = (const float*)d_in[3];
    const float* bc1 = (const float*)d_in[4];
    const float* Wc2 = (const float*)d_in[5];
    const float* bc2 = (const float*)d_in[6];
    const float* Wl1 = (const float*)d_in[7];
    const float* bl1 = (const float*)d_in[8];
    const float* Wl2 = (const float*)d_in[9];
    const float* bl2 = (const float*)d_in[10];
    const float* Wm1 = (const float*)d_in[11];
    const float* bm1 = (const float*)d_in[12];
    const float* Wm2 = (const float*)d_in[13];
    const float* bm2 = (const float*)d_in[14];
    float* out = (float*)d_out;

    cudaFuncSetAttribute(gemm_tc, cudaFuncAttributeMaxDynamicSharedMemorySize, SMEMSZ);

    static cudaStream_t s2 = nullptr;
    static cudaEvent_t evFork = nullptr, evJoin = nullptr;
    if (s2 == nullptr) {
        cudaStreamCreateWithFlags(&s2, cudaStreamNonBlocking);
        cudaEventCreateWithFlags(&evFork, cudaEventDisableTiming);
        cudaEventCreateWithFlags(&evJoin, cudaEventDisableTiming);
    }

    __half *Sc2, *Sl2, *x2, *a2, *b2;
    float *part, *z1f, *v0, *v1, *y16, *hp;
    cudaGetSymbolAddress((void**)&Sc2, g_Sc2); cudaGetSymbolAddress((void**)&Sl2, g_Sl2);
    cudaGetSymbolAddress((void**)&x2, g_x2);
    cudaGetSymbolAddress((void**)&a2, g_a2);   cudaGetSymbolAddress((void**)&b2, g_b2);
    cudaGetSymbolAddress((void**)&part, g_part);
    cudaGetSymbolAddress((void**)&z1f, g_z1f);
    cudaGetSymbolAddress((void**)&v0, g_v0);   cudaGetSymbolAddress((void**)&v1, g_v1);
    cudaGetSymbolAddress((void**)&y16, g_y16);
    cudaGetSymbolAddress((void**)&hp, g_hp);

    const int SN8 = NNODES * NNODES / 8;
    const int XN8 = CC * NNODES / 8;

    // fork: convert Sl on the side stream (needed only from layer 3)
    cudaEventRecord(evFork, 0);
    cudaStreamWaitEvent(s2, evFork, 0);
    cvtS<<<SN8 / 256, 256, 0, s2>>>((const float4*)Sl, Sl2, SN8);
    cudaEventRecord(evJoin, s2);

    cvtS<<<SN8 / 256, 256>>>((const float4*)Sc, Sc2, SN8);
    cvtA<<<XN8 / 256, 256>>>((const float4*)x,  x2,  XN8);

    const dim3 gG(NNODES / NT, SPLITK);           // 64 x 4 = 256 CTAs
    const dim3 gR(CC * NNODES / 8 / 256);         // 256 blocks
    const dim3 gF(NNODES / 256, BATCH);           // 16 x 8 fused head

    // ---- Layer 1 (clique, 16 -> 32) + Layer-2 projections, fused ----
    gemm_tc<<<gG, 256, SMEMSZ>>>(x2, Sc2, part);
    reduce_splitk<0><<<gR, 256>>>(part, nullptr, nullptr, z1f, a2);
    gemm_tc<<<gG, 256, SMEMSZ>>>(a2, Sc2, part);
    layer_fused<<<gF, 256>>>(part, z1f, x, Wc1, bc1, Wc2, v0, v1, b2);

    // ---- Layer 2 (clique, 32 -> 16): Horner ----
    gemm_tc<<<gG, 256, SMEMSZ>>>(b2, Sc2, part);
    reduce_splitk<1><<<gR, 256>>>(part, v1, nullptr, nullptr, a2);
    gemm_tc<<<gG, 256, SMEMSZ>>>(a2, Sc2, part);
    reduce_splitk<2><<<gR, 256>>>(part, v0, bc2, y16, b2);

    // join: Sl2 ready before the line layers
    cudaStreamWaitEvent(0, evJoin, 0);

    // ---- Layer 3 (line, 16 -> 32) + Layer-4 projections, fused ----
    gemm_tc<<<gG, 256, SMEMSZ>>>(b2, Sl2, part);
    reduce_splitk<0><<<gR, 256>>>(part, nullptr, nullptr, z1f, a2);
    gemm_tc<<<gG, 256, SMEMSZ>>>(a2, Sl2, part);
    layer_fused<<<gF, 256>>>(part, z1f, y16, Wl1, bl1, Wl2, v0, v1, b2);

    // ---- Layer 4 (line, 32 -> 16): Horner ----
    gemm_tc<<<gG, 256, SMEMSZ>>>(b2, Sl2, part);
    reduce_splitk<1><<<gR, 256>>>(part, v1, nullptr, nullptr, a2);
    gemm_tc<<<gG, 256, SMEMSZ>>>(a2, Sl2, part);
    reduce_splitk<2><<<gR, 256>>>(part, v0, bl2, y16, nullptr);

    // ---- MLP head ----
    mlp1b<<<dim3(8, 8), 256>>>(y16, Wm1, hp);
    mlp2b<<<BATCH, 64>>>(hp, bm1, Wm2, bm2, out);
}